// round 2
// baseline (speedup 1.0000x reference)
#include <cuda_runtime.h>
#include <math.h>

#define NN 50000
#define EE 1600000
#define FD 512
#define NC 40
#define KTOT 1536   // 3 * FD (t, s1, s2)

// ---------------- device scratch (static globals; no allocation) ----------------
__device__ float g_deg[NN];
__device__ float g_dinv[NN];
__device__ int   g_cnt[NN];
__device__ int   g_fill[NN];
__device__ int   g_rowptr[NN + 1];
__device__ int   g_csrcol[EE];
__device__ float g_t [(size_t)NN * FD];
__device__ float g_s1[(size_t)NN * FD];
__device__ float g_s2[(size_t)NN * FD];
__device__ float g_wr[KTOT * NC];

// ---------------- preprocessing ----------------
__global__ void k_init(int n) {
    int i = blockIdx.x * blockDim.x + threadIdx.x;
    if (i < n) { g_deg[i] = 1.0f; g_cnt[i] = 0; g_fill[i] = 0; }
}

__global__ void k_count(const int* __restrict__ row, const int* __restrict__ col, int e) {
    int i = blockIdx.x * blockDim.x + threadIdx.x;
    if (i < e) {
        atomicAdd(&g_deg[col[i]], 1.0f);
        atomicAdd(&g_cnt[row[i]], 1);
    }
}

__global__ void k_dinv(int n) {
    int i = blockIdx.x * blockDim.x + threadIdx.x;
    if (i < n) g_dinv[i] = rsqrtf(g_deg[i]);   // deg >= 1 always (self-loop)
}

// single-block exclusive scan of g_cnt -> g_rowptr (n up to NN)
__global__ void k_scan(int n) {
    __shared__ int sums[1024];
    int t = threadIdx.x;
    int chunk = (n + 1023) / 1024;
    int start = t * chunk;
    int end   = start + chunk; if (end > n) end = n;
    int s = 0;
    for (int i = start; i < end; i++) s += g_cnt[i];
    sums[t] = s;
    __syncthreads();
    for (int off = 1; off < 1024; off <<= 1) {
        int v = (t >= off) ? sums[t - off] : 0;
        __syncthreads();
        sums[t] += v;
        __syncthreads();
    }
    int run = (t == 0) ? 0 : sums[t - 1];
    for (int i = start; i < end; i++) { g_rowptr[i] = run; run += g_cnt[i]; }
    if (t == 1023) g_rowptr[n] = sums[1023];
}

__global__ void k_scatter(const int* __restrict__ row, const int* __restrict__ col, int e) {
    int i = blockIdx.x * blockDim.x + threadIdx.x;
    if (i < e) {
        int r = row[i];
        int pos = g_rowptr[r] + atomicAdd(&g_fill[r], 1);
        g_csrcol[pos] = col[i];
    }
}

// ---------------- GEMM1: t = relu(x @ W1 + b1)  [n,512]x[512,512] ----------------
// 128x128 block tile, 256 threads, 8x8 microtile, k-tile 8.
__global__ void k_gemm1(const float* __restrict__ A, const float* __restrict__ B,
                        const float* __restrict__ bias, int n) {
    __shared__ float As[8][128];
    __shared__ float Bs[8][128];
    int tid = threadIdx.x;
    int r0 = blockIdx.x * 128;
    int c0 = blockIdx.y * 128;
    int ty = tid / 16;       // 0..15 -> rows ty*8..+7
    int tx = tid % 16;       // 0..15 -> cols tx*8..+7

    float acc[8][8];
#pragma unroll
    for (int i = 0; i < 8; i++)
#pragma unroll
        for (int j = 0; j < 8; j++) acc[i][j] = 0.f;

    int arow = tid / 2;            // 0..127
    int akq  = (tid & 1) * 4;      // 0 or 4
    int brow = tid / 32;           // 0..7
    int bcq  = (tid % 32) * 4;     // 0..124

    for (int k0 = 0; k0 < FD; k0 += 8) {
        float4 av;
        int gr = r0 + arow;
        if (gr < n) av = *(const float4*)(A + (size_t)gr * FD + k0 + akq);
        else        av = make_float4(0.f, 0.f, 0.f, 0.f);
        As[akq + 0][arow] = av.x;
        As[akq + 1][arow] = av.y;
        As[akq + 2][arow] = av.z;
        As[akq + 3][arow] = av.w;

        float4 bv = *(const float4*)(B + (size_t)(k0 + brow) * FD + c0 + bcq);
        *(float4*)&Bs[brow][bcq] = bv;
        __syncthreads();

#pragma unroll
        for (int kk = 0; kk < 8; kk++) {
            float a[8], b[8];
            float4 a0 = *(float4*)&As[kk][ty * 8];
            float4 a1 = *(float4*)&As[kk][ty * 8 + 4];
            float4 b0 = *(float4*)&Bs[kk][tx * 8];
            float4 b1 = *(float4*)&Bs[kk][tx * 8 + 4];
            a[0]=a0.x; a[1]=a0.y; a[2]=a0.z; a[3]=a0.w;
            a[4]=a1.x; a[5]=a1.y; a[6]=a1.z; a[7]=a1.w;
            b[0]=b0.x; b[1]=b0.y; b[2]=b0.z; b[3]=b0.w;
            b[4]=b1.x; b[5]=b1.y; b[6]=b1.z; b[7]=b1.w;
#pragma unroll
            for (int i = 0; i < 8; i++)
#pragma unroll
                for (int j = 0; j < 8; j++) acc[i][j] += a[i] * b[j];
        }
        __syncthreads();
    }

    // epilogue: bias + relu
    int col = c0 + tx * 8;
    float4 bb0 = *(const float4*)(bias + col);
    float4 bb1 = *(const float4*)(bias + col + 4);
    float bbv[8] = {bb0.x, bb0.y, bb0.z, bb0.w, bb1.x, bb1.y, bb1.z, bb1.w};
#pragma unroll
    for (int i = 0; i < 8; i++) {
        int gr = r0 + ty * 8 + i;
        if (gr < n) {
            float4 o0, o1;
            o0.x = fmaxf(acc[i][0] + bbv[0], 0.f);
            o0.y = fmaxf(acc[i][1] + bbv[1], 0.f);
            o0.z = fmaxf(acc[i][2] + bbv[2], 0.f);
            o0.w = fmaxf(acc[i][3] + bbv[3], 0.f);
            o1.x = fmaxf(acc[i][4] + bbv[4], 0.f);
            o1.y = fmaxf(acc[i][5] + bbv[5], 0.f);
            o1.z = fmaxf(acc[i][6] + bbv[6], 0.f);
            o1.w = fmaxf(acc[i][7] + bbv[7], 0.f);
            *(float4*)(g_t + (size_t)gr * FD + col)     = o0;
            *(float4*)(g_t + (size_t)gr * FD + col + 4) = o1;
        }
    }
}

// ---------------- CSR SpMM: out = D^-1/2 (A+I) D^-1/2 @ tin ----------------
// one block (128 thr) per node; each thread owns one float4 of the 512-wide row
__global__ void k_spmm(int which) {
    const float* __restrict__ tin = (which == 0) ? g_t  : g_s1;
    float*       __restrict__ out = (which == 0) ? g_s1 : g_s2;
    int i   = blockIdx.x;
    int tid = threadIdx.x;

    float di = g_dinv[i];
    const float4* t4 = (const float4*)tin;
    float4 s = t4[(size_t)i * 128 + tid];
    float w0 = di * di;
    float ax = s.x * w0, ay = s.y * w0, az = s.z * w0, aw = s.w * w0;

    int beg = g_rowptr[i], end = g_rowptr[i + 1];
    __shared__ int   sc[128];
    __shared__ float sw[128];

    for (int base = beg; base < end; base += 128) {
        int m = end - base; if (m > 128) m = 128;
        __syncthreads();
        if (tid < m) {
            int c = g_csrcol[base + tid];
            sc[tid] = c;
            sw[tid] = di * g_dinv[c];
        }
        __syncthreads();
        int j = 0;
        for (; j + 4 <= m; j += 4) {
            int   c0 = sc[j], c1 = sc[j+1], c2 = sc[j+2], c3 = sc[j+3];
            float x0 = sw[j], x1 = sw[j+1], x2 = sw[j+2], x3 = sw[j+3];
            float4 v0 = t4[(size_t)c0 * 128 + tid];
            float4 v1 = t4[(size_t)c1 * 128 + tid];
            float4 v2 = t4[(size_t)c2 * 128 + tid];
            float4 v3 = t4[(size_t)c3 * 128 + tid];
            ax += x0 * v0.x; ay += x0 * v0.y; az += x0 * v0.z; aw += x0 * v0.w;
            ax += x1 * v1.x; ay += x1 * v1.y; az += x1 * v1.z; aw += x1 * v1.w;
            ax += x2 * v2.x; ay += x2 * v2.y; az += x2 * v2.z; aw += x2 * v2.w;
            ax += x3 * v3.x; ay += x3 * v3.y; az += x3 * v3.z; aw += x3 * v3.w;
        }
        for (; j < m; j++) {
            int c = sc[j]; float w = sw[j];
            float4 v = t4[(size_t)c * 128 + tid];
            ax += w * v.x; ay += w * v.y; az += w * v.z; aw += w * v.w;
        }
    }
    ((float4*)out)[(size_t)i * 128 + tid] = make_float4(ax, ay, az, aw);
}

// ---------------- reduced final weight Wr [1536,40] ----------------
// h = [t, t, s1, s1, s2]  =>  Wr = [W2_0+W2_1 ; W2_2+W2_3 ; W2_4]
__global__ void k_buildwr(const float* __restrict__ W2) {
    int idx = blockIdx.x * blockDim.x + threadIdx.x;
    if (idx >= KTOT * NC) return;
    int k = idx / NC, c = idx % NC;
    float v;
    if (k < 512)       v = W2[k * NC + c]          + W2[(k + 512)  * NC + c];
    else if (k < 1024) v = W2[(k + 512) * NC + c]  + W2[(k + 1024) * NC + c];
    else               v = W2[(k + 1024) * NC + c];
    g_wr[idx] = v;
}

// ---------------- fused GEMM2 + log_softmax ----------------
// 128 rows/block, 256 threads; K=1536 in tiles of 16 from {g_t,g_s1,g_s2}
__global__ void k_gemm2_lsm(const float* __restrict__ b2, float* __restrict__ out, int n) {
    __shared__ float As[16][128];
    __shared__ float Ws[16][NC];
    __shared__ float slog[128][NC + 1];
    __shared__ float smax[128], slse[128];

    int tid = threadIdx.x;
    int r0  = blockIdx.x * 128;
    int rg  = tid / 8;    // 0..31 -> rows rg*4..+3
    int cg  = tid % 8;    // 0..7  -> cols cg*5..+4

    float acc[4][5];
#pragma unroll
    for (int i = 0; i < 4; i++)
#pragma unroll
        for (int j = 0; j < 5; j++) acc[i][j] = 0.f;

    int arow = tid / 2;             // 0..127
    int akq  = (tid & 1) * 8;       // 0 or 8

    for (int kt = 0; kt < KTOT; kt += 16) {
        const float* src = (kt < 512) ? g_t : ((kt < 1024) ? g_s1 : g_s2);
        int kloc = kt & 511;
        {
            int gr = r0 + arow;
            float4 v0, v1;
            if (gr < n) {
                const float4* p = (const float4*)(src + (size_t)gr * FD + kloc + akq);
                v0 = p[0]; v1 = p[1];
            } else {
                v0 = make_float4(0,0,0,0); v1 = v0;
            }
            As[akq + 0][arow] = v0.x; As[akq + 1][arow] = v0.y;
            As[akq + 2][arow] = v0.z; As[akq + 3][arow] = v0.w;
            As[akq + 4][arow] = v1.x; As[akq + 5][arow] = v1.y;
            As[akq + 6][arow] = v1.z; As[akq + 7][arow] = v1.w;
        }
        for (int idx = tid; idx < 16 * NC; idx += 256) {
            int kk = idx / NC, c = idx % NC;
            Ws[kk][c] = g_wr[(kt + kk) * NC + c];
        }
        __syncthreads();
#pragma unroll
        for (int kk = 0; kk < 16; kk++) {
            float a0 = As[kk][rg * 4 + 0];
            float a1 = As[kk][rg * 4 + 1];
            float a2 = As[kk][rg * 4 + 2];
            float a3 = As[kk][rg * 4 + 3];
            float w0 = Ws[kk][cg * 5 + 0];
            float w1 = Ws[kk][cg * 5 + 1];
            float w2 = Ws[kk][cg * 5 + 2];
            float w3 = Ws[kk][cg * 5 + 3];
            float w4 = Ws[kk][cg * 5 + 4];
            acc[0][0]+=a0*w0; acc[0][1]+=a0*w1; acc[0][2]+=a0*w2; acc[0][3]+=a0*w3; acc[0][4]+=a0*w4;
            acc[1][0]+=a1*w0; acc[1][1]+=a1*w1; acc[1][2]+=a1*w2; acc[1][3]+=a1*w3; acc[1][4]+=a1*w4;
            acc[2][0]+=a2*w0; acc[2][1]+=a2*w1; acc[2][2]+=a2*w2; acc[2][3]+=a2*w3; acc[2][4]+=a2*w4;
            acc[3][0]+=a3*w0; acc[3][1]+=a3*w1; acc[3][2]+=a3*w2; acc[3][3]+=a3*w3; acc[3][4]+=a3*w4;
        }
        __syncthreads();
    }

    // logits -> smem (+bias)
#pragma unroll
    for (int i = 0; i < 4; i++)
#pragma unroll
        for (int j = 0; j < 5; j++)
            slog[rg * 4 + i][cg * 5 + j] = acc[i][j] + b2[cg * 5 + j];
    __syncthreads();

    if (tid < 128) {
        float m = -1e30f;
#pragma unroll
        for (int c = 0; c < NC; c++) m = fmaxf(m, slog[tid][c]);
        float s = 0.f;
#pragma unroll
        for (int c = 0; c < NC; c++) s += expf(slog[tid][c] - m);
        smax[tid] = m;
        slse[tid] = logf(s);
    }
    __syncthreads();

    for (int idx = tid; idx < 128 * NC; idx += 256) {
        int r = idx / NC, c = idx % NC;
        int gr = r0 + r;
        if (gr < n) out[(size_t)gr * NC + c] = slog[r][c] - smax[r] - slse[r];
    }
}

// ---------------- launch ----------------
extern "C" void kernel_launch(void* const* d_in, const int* in_sizes, int n_in,
                              void* d_out, int out_size) {
    const float* x    = (const float*)d_in[0];
    const int*   erow = (const int*)  d_in[1];
    const int*   ecol = (const int*)  d_in[2];
    const float* W1   = (const float*)d_in[3];
    const float* b1   = (const float*)d_in[4];
    const float* W2   = (const float*)d_in[5];
    const float* b2   = (const float*)d_in[6];
    float* out = (float*)d_out;

    int n = in_sizes[0] / FD;   // 50000
    int e = in_sizes[1];        // 1600000
    (void)n_in; (void)out_size;

    // 1) degree / dinv / CSR build
    k_init   <<<(n + 255) / 256, 256>>>(n);
    k_count  <<<(e + 255) / 256, 256>>>(erow, ecol, e);
    k_dinv   <<<(n + 255) / 256, 256>>>(n);
    k_scan   <<<1, 1024>>>(n);
    k_scatter<<<(e + 255) / 256, 256>>>(erow, ecol, e);

    // 2) t = relu(x @ W1 + b1)
    dim3 g1((n + 127) / 128, FD / 128);
    k_gemm1<<<g1, 256>>>(x, W1, b1, n);

    // 3) s1 = Ahat @ t ; s2 = Ahat @ s1
    k_spmm<<<n, 128>>>(0);
    k_spmm<<<n, 128>>>(1);

    // 4) reduced weights, fused final GEMM + log_softmax
    k_buildwr<<<(KTOT * NC + 255) / 256, 256>>>(W2);
    k_gemm2_lsm<<<(n + 127) / 128, 256>>>(b2, out, n);
}

// round 3
// speedup vs baseline: 1.3029x; 1.3029x over previous
#include <cuda_runtime.h>
#include <math.h>
#include <stdint.h>

#define NN 50000
#define EE 1600000
#define FD 512
#define NC 40
#define KTOT 1536   // 3 * FD (t, s1, s2)

// ---------------- device scratch (static globals; no allocation) ----------------
__device__ float g_deg[NN];
__device__ float g_dinv[NN];
__device__ __align__(16) int g_cnt[NN];
__device__ int   g_fill[NN];
__device__ int   g_rowptr[NN + 1];
__device__ int   g_csrcol[EE];
__device__ int   g_bsum[64];
__device__ __align__(16) float g_t [(size_t)NN * FD];
__device__ __align__(16) float g_s1[(size_t)NN * FD];
__device__ __align__(16) float g_s2[(size_t)NN * FD];
__device__ float g_wr[KTOT * NC];

// ---------------- preprocessing ----------------
__global__ void k_init(int n) {
    int i = blockIdx.x * blockDim.x + threadIdx.x;
    if (i < n) { g_deg[i] = 1.0f; g_cnt[i] = 0; g_fill[i] = 0; }
}

__global__ void k_count(const int* __restrict__ row, const int* __restrict__ col, int e) {
    int i = blockIdx.x * blockDim.x + threadIdx.x;
    if (i < e) {
        atomicAdd(&g_deg[col[i]], 1.0f);
        atomicAdd(&g_cnt[row[i]], 1);
    }
}

__global__ void k_dinv(int n) {
    int i = blockIdx.x * blockDim.x + threadIdx.x;
    if (i < n) g_dinv[i] = rsqrtf(g_deg[i]);   // deg >= 1 always (self-loop)
}

// ---- 3-phase exclusive scan of g_cnt -> g_rowptr ----
__global__ void k_scan1(int n) {
    __shared__ int sh[256];
    int b = blockIdx.x, t = threadIdx.x;
    int i = b * 1024 + t * 4;
    int s = 0;
    if (i + 3 < n) { int4 v = *(const int4*)(g_cnt + i); s = v.x + v.y + v.z + v.w; }
    else { for (int j = 0; j < 4; j++) if (i + j < n) s += g_cnt[i + j]; }
    sh[t] = s; __syncthreads();
    for (int o = 128; o > 0; o >>= 1) { if (t < o) sh[t] += sh[t + o]; __syncthreads(); }
    if (t == 0) g_bsum[b] = sh[0];
}

__global__ void k_scan2(int nb, int n) {
    int run = 0;
    for (int b = 0; b < nb; b++) { int v = g_bsum[b]; g_bsum[b] = run; run += v; }
    g_rowptr[n] = run;
}

__global__ void k_scan3(int n) {
    __shared__ int sh[256];
    int b = blockIdx.x, t = threadIdx.x;
    int i = b * 1024 + t * 4;
    int c0 = 0, c1 = 0, c2 = 0, c3 = 0;
    if (i + 3 < n) { int4 v = *(const int4*)(g_cnt + i); c0 = v.x; c1 = v.y; c2 = v.z; c3 = v.w; }
    else {
        if (i     < n) c0 = g_cnt[i];
        if (i + 1 < n) c1 = g_cnt[i + 1];
        if (i + 2 < n) c2 = g_cnt[i + 2];
        if (i + 3 < n) c3 = g_cnt[i + 3];
    }
    int s = c0 + c1 + c2 + c3;
    sh[t] = s; __syncthreads();
    for (int o = 1; o < 256; o <<= 1) {
        int v = (t >= o) ? sh[t - o] : 0;
        __syncthreads();
        sh[t] += v;
        __syncthreads();
    }
    int base = g_bsum[b] + ((t > 0) ? sh[t - 1] : 0);
    if (i     < n) { g_rowptr[i]     = base; base += c0; }
    if (i + 1 < n) { g_rowptr[i + 1] = base; base += c1; }
    if (i + 2 < n) { g_rowptr[i + 2] = base; base += c2; }
    if (i + 3 < n) { g_rowptr[i + 3] = base; }
}

__global__ void k_scatter(const int* __restrict__ row, const int* __restrict__ col, int e) {
    int i = blockIdx.x * blockDim.x + threadIdx.x;
    if (i < e) {
        int r = row[i];
        int pos = g_rowptr[r] + atomicAdd(&g_fill[r], 1);
        g_csrcol[pos] = col[i];
    }
}

// ---------------- TF32 tensor-core GEMM1: t = relu(x @ W1 + b1) ----------------
__device__ __forceinline__ uint32_t f2tf32(float f) {
    uint32_t u;
    asm("cvt.rna.tf32.f32 %0, %1;" : "=r"(u) : "f"(f));
    return u;
}

__device__ __forceinline__ void mma_tf32(float* d, const uint32_t* a, const uint32_t* b) {
    asm volatile(
        "mma.sync.aligned.m16n8k8.row.col.f32.tf32.tf32.f32 "
        "{%0,%1,%2,%3}, {%4,%5,%6,%7}, {%8,%9}, {%0,%1,%2,%3};\n"
        : "+f"(d[0]), "+f"(d[1]), "+f"(d[2]), "+f"(d[3])
        : "r"(a[0]), "r"(a[1]), "r"(a[2]), "r"(a[3]), "r"(b[0]), "r"(b[1]));
}

#define BM 128
#define BN 128
#define BK 16

__global__ __launch_bounds__(256, 2) void k_gemm1(const float* __restrict__ A,
                                                  const float* __restrict__ B,
                                                  const float* __restrict__ bias, int n) {
    __shared__ uint32_t As[BK][BM + 4];
    __shared__ uint32_t Bs[BK][BN + 4];
    int tid = threadIdx.x;
    int lane = tid & 31, warp = tid >> 5;
    int wm = (warp & 3) * 32;   // warp row offset in tile
    int wn = (warp >> 2) * 64;  // warp col offset in tile
    int r0 = blockIdx.x * BM, c0 = blockIdx.y * BN;

    float acc[2][8][4];
#pragma unroll
    for (int mi = 0; mi < 2; mi++)
#pragma unroll
        for (int ni = 0; ni < 8; ni++)
#pragma unroll
            for (int j = 0; j < 4; j++) acc[mi][ni][j] = 0.f;

    int arow = tid & 127;
    int ak4  = (tid >> 7) * 8;

    for (int k0 = 0; k0 < FD; k0 += BK) {
        // A tile 128x16 -> As[k][m] (transposed, tf32)
        int gr = r0 + arow;
        float4 av0, av1;
        if (gr < n) {
            const float4* p = (const float4*)(A + (size_t)gr * FD + k0 + ak4);
            av0 = p[0]; av1 = p[1];
        } else {
            av0 = make_float4(0, 0, 0, 0); av1 = av0;
        }
        As[ak4 + 0][arow] = f2tf32(av0.x);
        As[ak4 + 1][arow] = f2tf32(av0.y);
        As[ak4 + 2][arow] = f2tf32(av0.z);
        As[ak4 + 3][arow] = f2tf32(av0.w);
        As[ak4 + 4][arow] = f2tf32(av1.x);
        As[ak4 + 5][arow] = f2tf32(av1.y);
        As[ak4 + 6][arow] = f2tf32(av1.z);
        As[ak4 + 7][arow] = f2tf32(av1.w);

        // B tile 16x128 -> Bs[k][nn] (tf32)
#pragma unroll
        for (int rep = 0; rep < 2; rep++) {
            int i = tid + rep * 256;
            int bk = i >> 5, bc = (i & 31) * 4;
            float4 bv = *(const float4*)(B + (size_t)(k0 + bk) * FD + c0 + bc);
            Bs[bk][bc + 0] = f2tf32(bv.x);
            Bs[bk][bc + 1] = f2tf32(bv.y);
            Bs[bk][bc + 2] = f2tf32(bv.z);
            Bs[bk][bc + 3] = f2tf32(bv.w);
        }
        __syncthreads();

#pragma unroll
        for (int ks = 0; ks < BK; ks += 8) {
            uint32_t afr[2][4], bfr[8][2];
            int krow = ks + (lane & 3);
            int grp  = lane >> 2;
#pragma unroll
            for (int mi = 0; mi < 2; mi++) {
                int row = wm + mi * 16 + grp;
                afr[mi][0] = As[krow][row];
                afr[mi][1] = As[krow][row + 8];
                afr[mi][2] = As[krow + 4][row];
                afr[mi][3] = As[krow + 4][row + 8];
            }
#pragma unroll
            for (int ni = 0; ni < 8; ni++) {
                int col = wn + ni * 8 + grp;
                bfr[ni][0] = Bs[krow][col];
                bfr[ni][1] = Bs[krow + 4][col];
            }
#pragma unroll
            for (int mi = 0; mi < 2; mi++)
#pragma unroll
                for (int ni = 0; ni < 8; ni++)
                    mma_tf32(acc[mi][ni], afr[mi], bfr[ni]);
        }
        __syncthreads();
    }

    // epilogue: bias + relu -> g_t
    int grp = lane >> 2;
#pragma unroll
    for (int mi = 0; mi < 2; mi++) {
        int row = r0 + wm + mi * 16 + grp;
#pragma unroll
        for (int ni = 0; ni < 8; ni++) {
            int col = c0 + wn + ni * 8 + (lane & 3) * 2;
            float bb0 = bias[col], bb1 = bias[col + 1];
            if (row < n) {
                float2 v;
                v.x = fmaxf(acc[mi][ni][0] + bb0, 0.f);
                v.y = fmaxf(acc[mi][ni][1] + bb1, 0.f);
                *(float2*)(g_t + (size_t)row * FD + col) = v;
            }
            if (row + 8 < n) {
                float2 v;
                v.x = fmaxf(acc[mi][ni][2] + bb0, 0.f);
                v.y = fmaxf(acc[mi][ni][3] + bb1, 0.f);
                *(float2*)(g_t + (size_t)(row + 8) * FD + col) = v;
            }
        }
    }
}

// ---------------- CSR SpMM: out = D^-1/2 (A+I) D^-1/2 @ tin ----------------
__global__ void k_spmm(int which) {
    const float* __restrict__ tin = (which == 0) ? g_t  : g_s1;
    float*       __restrict__ out = (which == 0) ? g_s1 : g_s2;
    int i   = blockIdx.x;
    int tid = threadIdx.x;

    float di = g_dinv[i];
    const float4* t4 = (const float4*)tin;
    float4 s = t4[(size_t)i * 128 + tid];
    float w0 = di * di;
    float ax = s.x * w0, ay = s.y * w0, az = s.z * w0, aw = s.w * w0;

    int beg = g_rowptr[i], end = g_rowptr[i + 1];
    __shared__ int   sc[128];
    __shared__ float sw[128];

    for (int base = beg; base < end; base += 128) {
        int m = end - base; if (m > 128) m = 128;
        __syncthreads();
        if (tid < m) {
            int c = g_csrcol[base + tid];
            sc[tid] = c;
            sw[tid] = di * g_dinv[c];
        }
        __syncthreads();
        int j = 0;
        for (; j + 4 <= m; j += 4) {
            int   c0 = sc[j], c1 = sc[j+1], c2 = sc[j+2], c3 = sc[j+3];
            float x0 = sw[j], x1 = sw[j+1], x2 = sw[j+2], x3 = sw[j+3];
            float4 v0 = t4[(size_t)c0 * 128 + tid];
            float4 v1 = t4[(size_t)c1 * 128 + tid];
            float4 v2 = t4[(size_t)c2 * 128 + tid];
            float4 v3 = t4[(size_t)c3 * 128 + tid];
            ax += x0 * v0.x; ay += x0 * v0.y; az += x0 * v0.z; aw += x0 * v0.w;
            ax += x1 * v1.x; ay += x1 * v1.y; az += x1 * v1.z; aw += x1 * v1.w;
            ax += x2 * v2.x; ay += x2 * v2.y; az += x2 * v2.z; aw += x2 * v2.w;
            ax += x3 * v3.x; ay += x3 * v3.y; az += x3 * v3.z; aw += x3 * v3.w;
        }
        for (; j < m; j++) {
            int c = sc[j]; float w = sw[j];
            float4 v = t4[(size_t)c * 128 + tid];
            ax += w * v.x; ay += w * v.y; az += w * v.z; aw += w * v.w;
        }
    }
    ((float4*)out)[(size_t)i * 128 + tid] = make_float4(ax, ay, az, aw);
}

// ---------------- reduced final weight Wr [1536,40] ----------------
__global__ void k_buildwr(const float* __restrict__ W2) {
    int idx = blockIdx.x * blockDim.x + threadIdx.x;
    if (idx >= KTOT * NC) return;
    int k = idx / NC, c = idx % NC;
    float v;
    if (k < 512)       v = W2[k * NC + c]          + W2[(k + 512)  * NC + c];
    else if (k < 1024) v = W2[(k + 512) * NC + c]  + W2[(k + 1024) * NC + c];
    else               v = W2[(k + 1024) * NC + c];
    g_wr[idx] = v;
}

// ---------------- fused GEMM2 + log_softmax ----------------
__global__ void k_gemm2_lsm(const float* __restrict__ b2, float* __restrict__ out, int n) {
    __shared__ float As[16][128];
    __shared__ float Ws[16][NC];
    __shared__ float slog[128][NC + 1];
    __shared__ float smax[128], slse[128];

    int tid = threadIdx.x;
    int r0  = blockIdx.x * 128;
    int rg  = tid / 8;
    int cg  = tid % 8;

    float acc[4][5];
#pragma unroll
    for (int i = 0; i < 4; i++)
#pragma unroll
        for (int j = 0; j < 5; j++) acc[i][j] = 0.f;

    int arow = tid / 2;
    int akq  = (tid & 1) * 8;

    for (int kt = 0; kt < KTOT; kt += 16) {
        const float* src = (kt < 512) ? g_t : ((kt < 1024) ? g_s1 : g_s2);
        int kloc = kt & 511;
        {
            int gr = r0 + arow;
            float4 v0, v1;
            if (gr < n) {
                const float4* p = (const float4*)(src + (size_t)gr * FD + kloc + akq);
                v0 = p[0]; v1 = p[1];
            } else {
                v0 = make_float4(0,0,0,0); v1 = v0;
            }
            As[akq + 0][arow] = v0.x; As[akq + 1][arow] = v0.y;
            As[akq + 2][arow] = v0.z; As[akq + 3][arow] = v0.w;
            As[akq + 4][arow] = v1.x; As[akq + 5][arow] = v1.y;
            As[akq + 6][arow] = v1.z; As[akq + 7][arow] = v1.w;
        }
        for (int idx = tid; idx < 16 * NC; idx += 256) {
            int kk = idx / NC, c = idx % NC;
            Ws[kk][c] = g_wr[(kt + kk) * NC + c];
        }
        __syncthreads();
#pragma unroll
        for (int kk = 0; kk < 16; kk++) {
            float a0 = As[kk][rg * 4 + 0];
            float a1 = As[kk][rg * 4 + 1];
            float a2 = As[kk][rg * 4 + 2];
            float a3 = As[kk][rg * 4 + 3];
            float w0 = Ws[kk][cg * 5 + 0];
            float w1 = Ws[kk][cg * 5 + 1];
            float w2 = Ws[kk][cg * 5 + 2];
            float w3 = Ws[kk][cg * 5 + 3];
            float w4 = Ws[kk][cg * 5 + 4];
            acc[0][0]+=a0*w0; acc[0][1]+=a0*w1; acc[0][2]+=a0*w2; acc[0][3]+=a0*w3; acc[0][4]+=a0*w4;
            acc[1][0]+=a1*w0; acc[1][1]+=a1*w1; acc[1][2]+=a1*w2; acc[1][3]+=a1*w3; acc[1][4]+=a1*w4;
            acc[2][0]+=a2*w0; acc[2][1]+=a2*w1; acc[2][2]+=a2*w2; acc[2][3]+=a2*w3; acc[2][4]+=a2*w4;
            acc[3][0]+=a3*w0; acc[3][1]+=a3*w1; acc[3][2]+=a3*w2; acc[3][3]+=a3*w3; acc[3][4]+=a3*w4;
        }
        __syncthreads();
    }

#pragma unroll
    for (int i = 0; i < 4; i++)
#pragma unroll
        for (int j = 0; j < 5; j++)
            slog[rg * 4 + i][cg * 5 + j] = acc[i][j] + b2[cg * 5 + j];
    __syncthreads();

    if (tid < 128) {
        float m = -1e30f;
#pragma unroll
        for (int c = 0; c < NC; c++) m = fmaxf(m, slog[tid][c]);
        float s = 0.f;
#pragma unroll
        for (int c = 0; c < NC; c++) s += expf(slog[tid][c] - m);
        smax[tid] = m;
        slse[tid] = logf(s);
    }
    __syncthreads();

    for (int idx = tid; idx < 128 * NC; idx += 256) {
        int r = idx / NC, c = idx % NC;
        int gr = r0 + r;
        if (gr < n) out[(size_t)gr * NC + c] = slog[r][c] - smax[r] - slse[r];
    }
}

// ---------------- launch ----------------
extern "C" void kernel_launch(void* const* d_in, const int* in_sizes, int n_in,
                              void* d_out, int out_size) {
    const float* x    = (const float*)d_in[0];
    const int*   erow = (const int*)  d_in[1];
    const int*   ecol = (const int*)  d_in[2];
    const float* W1   = (const float*)d_in[3];
    const float* b1   = (const float*)d_in[4];
    const float* W2   = (const float*)d_in[5];
    const float* b2   = (const float*)d_in[6];
    float* out = (float*)d_out;

    int n = in_sizes[0] / FD;   // 50000
    int e = in_sizes[1];        // 1600000
    (void)n_in; (void)out_size;

    int nb = (n + 1023) / 1024;

    // 1) degree / dinv / CSR build
    k_init   <<<(n + 255) / 256, 256>>>(n);
    k_count  <<<(e + 255) / 256, 256>>>(erow, ecol, e);
    k_dinv   <<<(n + 255) / 256, 256>>>(n);
    k_scan1  <<<nb, 256>>>(n);
    k_scan2  <<<1, 1>>>(nb, n);
    k_scan3  <<<nb, 256>>>(n);
    k_scatter<<<(e + 255) / 256, 256>>>(erow, ecol, e);

    // 2) t = relu(x @ W1 + b1)  [TF32 tensor cores]
    dim3 g1((n + 127) / 128, FD / 128);
    k_gemm1<<<g1, 256>>>(x, W1, b1, n);

    // 3) s1 = Ahat @ t ; s2 = Ahat @ s1
    k_spmm<<<n, 128>>>(0);
    k_spmm<<<n, 128>>>(1);

    // 4) reduced weights, fused final GEMM + log_softmax
    k_buildwr<<<(KTOT * NC + 255) / 256, 256>>>(W2);
    k_gemm2_lsm<<<(n + 127) / 128, 256>>>(b2, out, n);
}

// round 4
// speedup vs baseline: 1.6438x; 1.2617x over previous
#include <cuda_runtime.h>
#include <cuda_bf16.h>
#include <math.h>
#include <stdint.h>

#define NN 50000
#define EE 1600000
#define FD 512
#define NC 40
#define KTOT 1536   // 3 * FD (t, s1, s2)

// ---------------- device scratch (static globals; no allocation) ----------------
__device__ float g_deg[NN];
__device__ float g_dinv[NN];
__device__ __align__(16) int g_cnt[NN];
__device__ int   g_fill[NN];
__device__ int   g_rowptr[NN + 1];
__device__ int   g_csrcol[EE];
__device__ int   g_bsum[64];
__device__ __align__(16) float g_t [(size_t)NN * FD];
__device__ __align__(16) float g_s1[(size_t)NN * FD];
__device__ __align__(16) float g_s2[(size_t)NN * FD];
__device__ __align__(16) __nv_bfloat16 g_tb [(size_t)NN * FD];
__device__ __align__(16) __nv_bfloat16 g_s1b[(size_t)NN * FD];
__device__ uint32_t g_wr[KTOT * NC];   // tf32 bits

// ---------------- preprocessing ----------------
__global__ void k_init(int n) {
    int i = blockIdx.x * blockDim.x + threadIdx.x;
    if (i < n) { g_deg[i] = 1.0f; g_cnt[i] = 0; g_fill[i] = 0; }
}

__global__ void k_count(const int* __restrict__ row, const int* __restrict__ col, int e) {
    int i = blockIdx.x * blockDim.x + threadIdx.x;
    if (i < e) {
        atomicAdd(&g_deg[col[i]], 1.0f);
        atomicAdd(&g_cnt[row[i]], 1);
    }
}

__global__ void k_dinv(int n) {
    int i = blockIdx.x * blockDim.x + threadIdx.x;
    if (i < n) g_dinv[i] = rsqrtf(g_deg[i]);   // deg >= 1 always (self-loop)
}

// ---- 3-phase exclusive scan of g_cnt -> g_rowptr ----
__global__ void k_scan1(int n) {
    __shared__ int sh[256];
    int b = blockIdx.x, t = threadIdx.x;
    int i = b * 1024 + t * 4;
    int s = 0;
    if (i + 3 < n) { int4 v = *(const int4*)(g_cnt + i); s = v.x + v.y + v.z + v.w; }
    else { for (int j = 0; j < 4; j++) if (i + j < n) s += g_cnt[i + j]; }
    sh[t] = s; __syncthreads();
    for (int o = 128; o > 0; o >>= 1) { if (t < o) sh[t] += sh[t + o]; __syncthreads(); }
    if (t == 0) g_bsum[b] = sh[0];
}

__global__ void k_scan2(int nb, int n) {
    int run = 0;
    for (int b = 0; b < nb; b++) { int v = g_bsum[b]; g_bsum[b] = run; run += v; }
    g_rowptr[n] = run;
}

__global__ void k_scan3(int n) {
    __shared__ int sh[256];
    int b = blockIdx.x, t = threadIdx.x;
    int i = b * 1024 + t * 4;
    int c0 = 0, c1 = 0, c2 = 0, c3 = 0;
    if (i + 3 < n) { int4 v = *(const int4*)(g_cnt + i); c0 = v.x; c1 = v.y; c2 = v.z; c3 = v.w; }
    else {
        if (i     < n) c0 = g_cnt[i];
        if (i + 1 < n) c1 = g_cnt[i + 1];
        if (i + 2 < n) c2 = g_cnt[i + 2];
        if (i + 3 < n) c3 = g_cnt[i + 3];
    }
    int s = c0 + c1 + c2 + c3;
    sh[t] = s; __syncthreads();
    for (int o = 1; o < 256; o <<= 1) {
        int v = (t >= o) ? sh[t - o] : 0;
        __syncthreads();
        sh[t] += v;
        __syncthreads();
    }
    int base = g_bsum[b] + ((t > 0) ? sh[t - 1] : 0);
    if (i     < n) { g_rowptr[i]     = base; base += c0; }
    if (i + 1 < n) { g_rowptr[i + 1] = base; base += c1; }
    if (i + 2 < n) { g_rowptr[i + 2] = base; base += c2; }
    if (i + 3 < n) { g_rowptr[i + 3] = base; }
}

__global__ void k_scatter(const int* __restrict__ row, const int* __restrict__ col, int e) {
    int i = blockIdx.x * blockDim.x + threadIdx.x;
    if (i < e) {
        int r = row[i];
        int pos = g_rowptr[r] + atomicAdd(&g_fill[r], 1);
        g_csrcol[pos] = col[i];
    }
}

// ---------------- TF32 helpers ----------------
__device__ __forceinline__ uint32_t f2tf32(float f) {
    uint32_t u;
    asm("cvt.rna.tf32.f32 %0, %1;" : "=r"(u) : "f"(f));
    return u;
}

__device__ __forceinline__ void mma_tf32(float* d, const uint32_t* a, const uint32_t* b) {
    asm volatile(
        "mma.sync.aligned.m16n8k8.row.col.f32.tf32.tf32.f32 "
        "{%0,%1,%2,%3}, {%4,%5,%6,%7}, {%8,%9}, {%0,%1,%2,%3};\n"
        : "+f"(d[0]), "+f"(d[1]), "+f"(d[2]), "+f"(d[3])
        : "r"(a[0]), "r"(a[1]), "r"(a[2]), "r"(a[3]), "r"(b[0]), "r"(b[1]));
}

// ---------------- TF32 tensor-core GEMM1: t = relu(x @ W1 + b1) ----------------
#define BM 128
#define BN 128
#define BK 16

__global__ __launch_bounds__(256, 2) void k_gemm1(const float* __restrict__ A,
                                                  const float* __restrict__ B,
                                                  const float* __restrict__ bias, int n) {
    __shared__ uint32_t As[BK][BM + 4];
    __shared__ uint32_t Bs[BK][BN + 4];
    int tid = threadIdx.x;
    int lane = tid & 31, warp = tid >> 5;
    int wm = (warp & 3) * 32;
    int wn = (warp >> 2) * 64;
    int r0 = blockIdx.x * BM, c0 = blockIdx.y * BN;

    float acc[2][8][4];
#pragma unroll
    for (int mi = 0; mi < 2; mi++)
#pragma unroll
        for (int ni = 0; ni < 8; ni++)
#pragma unroll
            for (int j = 0; j < 4; j++) acc[mi][ni][j] = 0.f;

    int arow = tid & 127;
    int ak4  = (tid >> 7) * 8;

    for (int k0 = 0; k0 < FD; k0 += BK) {
        int gr = r0 + arow;
        float4 av0, av1;
        if (gr < n) {
            const float4* p = (const float4*)(A + (size_t)gr * FD + k0 + ak4);
            av0 = p[0]; av1 = p[1];
        } else {
            av0 = make_float4(0, 0, 0, 0); av1 = av0;
        }
        As[ak4 + 0][arow] = f2tf32(av0.x);
        As[ak4 + 1][arow] = f2tf32(av0.y);
        As[ak4 + 2][arow] = f2tf32(av0.z);
        As[ak4 + 3][arow] = f2tf32(av0.w);
        As[ak4 + 4][arow] = f2tf32(av1.x);
        As[ak4 + 5][arow] = f2tf32(av1.y);
        As[ak4 + 6][arow] = f2tf32(av1.z);
        As[ak4 + 7][arow] = f2tf32(av1.w);

#pragma unroll
        for (int rep = 0; rep < 2; rep++) {
            int i = tid + rep * 256;
            int bk = i >> 5, bc = (i & 31) * 4;
            float4 bv = *(const float4*)(B + (size_t)(k0 + bk) * FD + c0 + bc);
            Bs[bk][bc + 0] = f2tf32(bv.x);
            Bs[bk][bc + 1] = f2tf32(bv.y);
            Bs[bk][bc + 2] = f2tf32(bv.z);
            Bs[bk][bc + 3] = f2tf32(bv.w);
        }
        __syncthreads();

#pragma unroll
        for (int ks = 0; ks < BK; ks += 8) {
            uint32_t afr[2][4], bfr[8][2];
            int krow = ks + (lane & 3);
            int grp  = lane >> 2;
#pragma unroll
            for (int mi = 0; mi < 2; mi++) {
                int row = wm + mi * 16 + grp;
                afr[mi][0] = As[krow][row];
                afr[mi][1] = As[krow][row + 8];
                afr[mi][2] = As[krow + 4][row];
                afr[mi][3] = As[krow + 4][row + 8];
            }
#pragma unroll
            for (int ni = 0; ni < 8; ni++) {
                int col = wn + ni * 8 + grp;
                bfr[ni][0] = Bs[krow][col];
                bfr[ni][1] = Bs[krow + 4][col];
            }
#pragma unroll
            for (int mi = 0; mi < 2; mi++)
#pragma unroll
                for (int ni = 0; ni < 8; ni++)
                    mma_tf32(acc[mi][ni], afr[mi], bfr[ni]);
        }
        __syncthreads();
    }

    // epilogue: bias + relu -> g_t (fp32) + g_tb (bf16)
    int grp = lane >> 2;
#pragma unroll
    for (int mi = 0; mi < 2; mi++) {
        int row = r0 + wm + mi * 16 + grp;
#pragma unroll
        for (int ni = 0; ni < 8; ni++) {
            int col = c0 + wn + ni * 8 + (lane & 3) * 2;
            float bb0 = bias[col], bb1 = bias[col + 1];
            if (row < n) {
                float2 v;
                v.x = fmaxf(acc[mi][ni][0] + bb0, 0.f);
                v.y = fmaxf(acc[mi][ni][1] + bb1, 0.f);
                *(float2*)(g_t + (size_t)row * FD + col) = v;
                *(__nv_bfloat162*)(g_tb + (size_t)row * FD + col) = __floats2bfloat162_rn(v.x, v.y);
            }
            if (row + 8 < n) {
                float2 v;
                v.x = fmaxf(acc[mi][ni][2] + bb0, 0.f);
                v.y = fmaxf(acc[mi][ni][3] + bb1, 0.f);
                *(float2*)(g_t + (size_t)(row + 8) * FD + col) = v;
                *(__nv_bfloat162*)(g_tb + (size_t)(row + 8) * FD + col) = __floats2bfloat162_rn(v.x, v.y);
            }
        }
    }
}

// ---------------- CSR SpMM (bf16 gather, fp32 accumulate) ----------------
// one block (128 thr) per node; thread owns 4 consecutive features.
__global__ void k_spmm(int which) {
    const __nv_bfloat16* __restrict__ tb = (which == 0) ? g_tb : g_s1b;
    const float*         __restrict__ tf = (which == 0) ? g_t  : g_s1;
    float*               __restrict__ of = (which == 0) ? g_s1 : g_s2;
    __nv_bfloat16*       __restrict__ ob = (which == 0) ? g_s1b : (__nv_bfloat16*)0;

    int i   = blockIdx.x;
    int tid = threadIdx.x;

    float di = g_dinv[i];
    // self term in fp32
    float4 s = ((const float4*)tf)[(size_t)i * 128 + tid];
    float w0 = di * di;
    float ax = s.x * w0, ay = s.y * w0, az = s.z * w0, aw = s.w * w0;

    int beg = g_rowptr[i], end = g_rowptr[i + 1];
    __shared__ int   sc[128];
    __shared__ float sw[128];
    const uint2* t2 = (const uint2*)tb;

    for (int base = beg; base < end; base += 128) {
        int m = end - base; if (m > 128) m = 128;
        __syncthreads();
        if (tid < m) {
            int c = g_csrcol[base + tid];
            sc[tid] = c;
            sw[tid] = di * g_dinv[c];
        }
        __syncthreads();
        int j = 0;
        for (; j + 4 <= m; j += 4) {
            int   c0 = sc[j], c1 = sc[j+1], c2 = sc[j+2], c3 = sc[j+3];
            float x0 = sw[j], x1 = sw[j+1], x2 = sw[j+2], x3 = sw[j+3];
            uint2 v0 = t2[(size_t)c0 * 128 + tid];
            uint2 v1 = t2[(size_t)c1 * 128 + tid];
            uint2 v2 = t2[(size_t)c2 * 128 + tid];
            uint2 v3 = t2[(size_t)c3 * 128 + tid];
            ax += x0 * __uint_as_float(v0.x << 16);
            ay += x0 * __uint_as_float(v0.x & 0xffff0000u);
            az += x0 * __uint_as_float(v0.y << 16);
            aw += x0 * __uint_as_float(v0.y & 0xffff0000u);
            ax += x1 * __uint_as_float(v1.x << 16);
            ay += x1 * __uint_as_float(v1.x & 0xffff0000u);
            az += x1 * __uint_as_float(v1.y << 16);
            aw += x1 * __uint_as_float(v1.y & 0xffff0000u);
            ax += x2 * __uint_as_float(v2.x << 16);
            ay += x2 * __uint_as_float(v2.x & 0xffff0000u);
            az += x2 * __uint_as_float(v2.y << 16);
            aw += x2 * __uint_as_float(v2.y & 0xffff0000u);
            ax += x3 * __uint_as_float(v3.x << 16);
            ay += x3 * __uint_as_float(v3.x & 0xffff0000u);
            az += x3 * __uint_as_float(v3.y << 16);
            aw += x3 * __uint_as_float(v3.y & 0xffff0000u);
        }
        for (; j < m; j++) {
            int c = sc[j]; float w = sw[j];
            uint2 v = t2[(size_t)c * 128 + tid];
            ax += w * __uint_as_float(v.x << 16);
            ay += w * __uint_as_float(v.x & 0xffff0000u);
            az += w * __uint_as_float(v.y << 16);
            aw += w * __uint_as_float(v.y & 0xffff0000u);
        }
    }
    ((float4*)of)[(size_t)i * 128 + tid] = make_float4(ax, ay, az, aw);
    if (ob) {
        __nv_bfloat162 p0 = __floats2bfloat162_rn(ax, ay);
        __nv_bfloat162 p1 = __floats2bfloat162_rn(az, aw);
        uint2 pk;
        pk.x = *(uint32_t*)&p0;
        pk.y = *(uint32_t*)&p1;
        ((uint2*)ob)[(size_t)i * 128 + tid] = pk;
    }
}

// ---------------- reduced final weight Wr [1536,40] (tf32 bits) ----------------
__global__ void k_buildwr(const float* __restrict__ W2) {
    int idx = blockIdx.x * blockDim.x + threadIdx.x;
    if (idx >= KTOT * NC) return;
    int k = idx / NC, c = idx % NC;
    float v;
    if (k < 512)       v = W2[k * NC + c]          + W2[(k + 512)  * NC + c];
    else if (k < 1024) v = W2[(k + 512) * NC + c]  + W2[(k + 1024) * NC + c];
    else               v = W2[(k + 1024) * NC + c];
    g_wr[idx] = f2tf32(v);
}

// ---------------- fused TF32 GEMM2 + log_softmax ----------------
// 128 rows/block, 256 thr (8 warps, warp w owns rows w*16..+15), K=1536.
__global__ __launch_bounds__(256) void k_gemm2_lsm(const float* __restrict__ b2,
                                                   float* __restrict__ out, int n) {
    __shared__ uint32_t As[16][132];
    __shared__ uint32_t Ws[16][NC];

    int tid  = threadIdx.x;
    int lane = tid & 31, warp = tid >> 5;
    int r0   = blockIdx.x * 128;

    float acc[5][4];
#pragma unroll
    for (int t = 0; t < 5; t++)
#pragma unroll
        for (int j = 0; j < 4; j++) acc[t][j] = 0.f;

    int arow = tid & 127;
    int ak   = (tid >> 7) * 8;

    for (int kt = 0; kt < KTOT; kt += 16) {
        const float* src = (kt < 512) ? g_t : ((kt < 1024) ? g_s1 : g_s2);
        int kloc = kt & 511;
        {
            int gr = r0 + arow;
            float4 v0, v1;
            if (gr < n) {
                const float4* p = (const float4*)(src + (size_t)gr * FD + kloc + ak);
                v0 = p[0]; v1 = p[1];
            } else {
                v0 = make_float4(0, 0, 0, 0); v1 = v0;
            }
            As[ak + 0][arow] = f2tf32(v0.x);
            As[ak + 1][arow] = f2tf32(v0.y);
            As[ak + 2][arow] = f2tf32(v0.z);
            As[ak + 3][arow] = f2tf32(v0.w);
            As[ak + 4][arow] = f2tf32(v1.x);
            As[ak + 5][arow] = f2tf32(v1.y);
            As[ak + 6][arow] = f2tf32(v1.z);
            As[ak + 7][arow] = f2tf32(v1.w);
        }
        for (int idx = tid; idx < 16 * NC; idx += 256) {
            int kk = idx / NC, c = idx % NC;
            Ws[kk][c] = g_wr[(kt + kk) * NC + c];
        }
        __syncthreads();

#pragma unroll
        for (int ks = 0; ks < 16; ks += 8) {
            int krow = ks + (lane & 3);
            int grp  = lane >> 2;
            uint32_t a[4];
            int row = warp * 16 + grp;
            a[0] = As[krow][row];
            a[1] = As[krow][row + 8];
            a[2] = As[krow + 4][row];
            a[3] = As[krow + 4][row + 8];
#pragma unroll
            for (int t = 0; t < 5; t++) {
                uint32_t b[2];
                int col = t * 8 + grp;
                b[0] = Ws[krow][col];
                b[1] = Ws[krow + 4][col];
                mma_tf32(acc[t], a, b);
            }
        }
        __syncthreads();
    }

    // -------- epilogue: bias + log_softmax, all in-register --------
    int grp = lane >> 2, q = lane & 3;
    int rlo = r0 + warp * 16 + grp;
    int rhi = rlo + 8;

    float vlo[10], vhi[10];
#pragma unroll
    for (int t = 0; t < 5; t++) {
#pragma unroll
        for (int j = 0; j < 2; j++) {
            int col = t * 8 + q * 2 + j;
            float bb = b2[col];
            vlo[t * 2 + j] = acc[t][j]     + bb;
            vhi[t * 2 + j] = acc[t][j + 2] + bb;
        }
    }

    float mlo = -1e30f, mhi = -1e30f;
#pragma unroll
    for (int j = 0; j < 10; j++) { mlo = fmaxf(mlo, vlo[j]); mhi = fmaxf(mhi, vhi[j]); }
    mlo = fmaxf(mlo, __shfl_xor_sync(0xffffffffu, mlo, 1));
    mlo = fmaxf(mlo, __shfl_xor_sync(0xffffffffu, mlo, 2));
    mhi = fmaxf(mhi, __shfl_xor_sync(0xffffffffu, mhi, 1));
    mhi = fmaxf(mhi, __shfl_xor_sync(0xffffffffu, mhi, 2));

    float slo = 0.f, shi = 0.f;
#pragma unroll
    for (int j = 0; j < 10; j++) { slo += expf(vlo[j] - mlo); shi += expf(vhi[j] - mhi); }
    slo += __shfl_xor_sync(0xffffffffu, slo, 1);
    slo += __shfl_xor_sync(0xffffffffu, slo, 2);
    shi += __shfl_xor_sync(0xffffffffu, shi, 1);
    shi += __shfl_xor_sync(0xffffffffu, shi, 2);

    float zlo = mlo + logf(slo);
    float zhi = mhi + logf(shi);

    if (rlo < n) {
#pragma unroll
        for (int t = 0; t < 5; t++) {
            float2 v;
            v.x = vlo[t * 2]     - zlo;
            v.y = vlo[t * 2 + 1] - zlo;
            *(float2*)(out + (size_t)rlo * NC + t * 8 + q * 2) = v;
        }
    }
    if (rhi < n) {
#pragma unroll
        for (int t = 0; t < 5; t++) {
            float2 v;
            v.x = vhi[t * 2]     - zhi;
            v.y = vhi[t * 2 + 1] - zhi;
            *(float2*)(out + (size_t)rhi * NC + t * 8 + q * 2) = v;
        }
    }
}

// ---------------- launch ----------------
extern "C" void kernel_launch(void* const* d_in, const int* in_sizes, int n_in,
                              void* d_out, int out_size) {
    const float* x    = (const float*)d_in[0];
    const int*   erow = (const int*)  d_in[1];
    const int*   ecol = (const int*)  d_in[2];
    const float* W1   = (const float*)d_in[3];
    const float* b1   = (const float*)d_in[4];
    const float* W2   = (const float*)d_in[5];
    const float* b2   = (const float*)d_in[6];
    float* out = (float*)d_out;

    int n = in_sizes[0] / FD;   // 50000
    int e = in_sizes[1];        // 1600000
    (void)n_in; (void)out_size;

    int nb = (n + 1023) / 1024;

    // 1) degree / dinv / CSR build
    k_init   <<<(n + 255) / 256, 256>>>(n);
    k_count  <<<(e + 255) / 256, 256>>>(erow, ecol, e);
    k_dinv   <<<(n + 255) / 256, 256>>>(n);
    k_scan1  <<<nb, 256>>>(n);
    k_scan2  <<<1, 1>>>(nb, n);
    k_scan3  <<<nb, 256>>>(n);
    k_scatter<<<(e + 255) / 256, 256>>>(erow, ecol, e);

    // 2) t = relu(x @ W1 + b1)  [TF32 tensor cores] + bf16 shadow copy
    dim3 g1((n + 127) / 128, FD / 128);
    k_gemm1<<<g1, 256>>>(x, W1, b1, n);

    // 3) s1 = Ahat @ t ; s2 = Ahat @ s1  [bf16 gather, fp32 accumulate]
    k_spmm<<<n, 128>>>(0);
    k_spmm<<<n, 128>>>(1);

    // 4) reduced weights (tf32), fused TF32 GEMM + log_softmax
    k_buildwr<<<(KTOT * NC + 255) / 256, 256>>>(W2);
    k_gemm2_lsm<<<(n + 127) / 128, 256>>>(b2, out, n);
}

// round 6
// speedup vs baseline: 2.1970x; 1.3365x over previous
#include <cuda_runtime.h>
#include <math.h>
#include <stdint.h>

#define NN 50000
#define EE 1600000
#define FD 512
#define NC 40
#define NCOL 120   // [Wa|Wb|Wc] columns

// ---------------- device scratch ----------------
__device__ float g_deg[NN];
__device__ float g_dinv[NN];
__device__ __align__(16) int g_cnt[NN];
__device__ int   g_fill[NN];
__device__ int   g_rowptr[NN + 1];
__device__ int   g_csrcol[EE];
__device__ int   g_bsum[64];
__device__ __align__(16) float g_t  [(size_t)NN * FD];   // relu(xW1+b1)
__device__ __align__(16) float g_p0 [(size_t)NN * 40];   // t*Wa
__device__ __align__(16) float g_p12[(size_t)NN * 80];   // [t*Wb | t*Wc]
__device__ __align__(16) float g_q12[(size_t)NN * 80];   // [A p1 | A p2]
__device__ __align__(16) float g_r  [(size_t)NN * 40];   // A^2 p2
__device__ uint32_t g_wrall[FD * NCOL];                  // tf32 bits

// ---------------- preprocessing ----------------
__global__ void k_init(int n) {
    int i = blockIdx.x * blockDim.x + threadIdx.x;
    if (i < n) { g_deg[i] = 1.0f; g_cnt[i] = 0; g_fill[i] = 0; }
}

__global__ void k_count(const int* __restrict__ row, const int* __restrict__ col, int e) {
    int i = blockIdx.x * blockDim.x + threadIdx.x;
    if (i < e) {
        atomicAdd(&g_deg[col[i]], 1.0f);
        atomicAdd(&g_cnt[row[i]], 1);
    }
}

__global__ void k_dinv(int n) {
    int i = blockIdx.x * blockDim.x + threadIdx.x;
    if (i < n) g_dinv[i] = rsqrtf(g_deg[i]);
}

__global__ void k_scan1(int n) {
    __shared__ int sh[256];
    int b = blockIdx.x, t = threadIdx.x;
    int i = b * 1024 + t * 4;
    int s = 0;
    if (i + 3 < n) { int4 v = *(const int4*)(g_cnt + i); s = v.x + v.y + v.z + v.w; }
    else { for (int j = 0; j < 4; j++) if (i + j < n) s += g_cnt[i + j]; }
    sh[t] = s; __syncthreads();
    for (int o = 128; o > 0; o >>= 1) { if (t < o) sh[t] += sh[t + o]; __syncthreads(); }
    if (t == 0) g_bsum[b] = sh[0];
}

__global__ void k_scan2(int nb, int n) {
    int run = 0;
    for (int b = 0; b < nb; b++) { int v = g_bsum[b]; g_bsum[b] = run; run += v; }
    g_rowptr[n] = run;
}

__global__ void k_scan3(int n) {
    __shared__ int sh[256];
    int b = blockIdx.x, t = threadIdx.x;
    int i = b * 1024 + t * 4;
    int c0 = 0, c1 = 0, c2 = 0, c3 = 0;
    if (i + 3 < n) { int4 v = *(const int4*)(g_cnt + i); c0 = v.x; c1 = v.y; c2 = v.z; c3 = v.w; }
    else {
        if (i     < n) c0 = g_cnt[i];
        if (i + 1 < n) c1 = g_cnt[i + 1];
        if (i + 2 < n) c2 = g_cnt[i + 2];
        if (i + 3 < n) c3 = g_cnt[i + 3];
    }
    int s = c0 + c1 + c2 + c3;
    sh[t] = s; __syncthreads();
    for (int o = 1; o < 256; o <<= 1) {
        int v = (t >= o) ? sh[t - o] : 0;
        __syncthreads();
        sh[t] += v;
        __syncthreads();
    }
    int base = g_bsum[b] + ((t > 0) ? sh[t - 1] : 0);
    if (i     < n) { g_rowptr[i]     = base; base += c0; }
    if (i + 1 < n) { g_rowptr[i + 1] = base; base += c1; }
    if (i + 2 < n) { g_rowptr[i + 2] = base; base += c2; }
    if (i + 3 < n) { g_rowptr[i + 3] = base; }
}

__global__ void k_scatter(const int* __restrict__ row, const int* __restrict__ col, int e) {
    int i = blockIdx.x * blockDim.x + threadIdx.x;
    if (i < e) {
        int r = row[i];
        int pos = g_rowptr[r] + atomicAdd(&g_fill[r], 1);
        g_csrcol[pos] = col[i];
    }
}

// ---------------- TF32 helpers ----------------
__device__ __forceinline__ uint32_t f2tf32(float f) {
    uint32_t u;
    asm("cvt.rna.tf32.f32 %0, %1;" : "=r"(u) : "f"(f));
    return u;
}

__device__ __forceinline__ void mma_tf32(float* d, const uint32_t* a, const uint32_t* b) {
    asm volatile(
        "mma.sync.aligned.m16n8k8.row.col.f32.tf32.tf32.f32 "
        "{%0,%1,%2,%3}, {%4,%5,%6,%7}, {%8,%9}, {%0,%1,%2,%3};\n"
        : "+f"(d[0]), "+f"(d[1]), "+f"(d[2]), "+f"(d[3])
        : "r"(a[0]), "r"(a[1]), "r"(a[2]), "r"(a[3]), "r"(b[0]), "r"(b[1]));
}

// ---------------- TF32 GEMM1: t = relu(x @ W1 + b1) ----------------
#define BM 128
#define BN 128
#define BK 16

__global__ __launch_bounds__(256, 2) void k_gemm1(const float* __restrict__ A,
                                                  const float* __restrict__ B,
                                                  const float* __restrict__ bias, int n) {
    __shared__ uint32_t As[BK][BM + 4];
    __shared__ uint32_t Bs[BK][BN + 4];
    int tid = threadIdx.x;
    int lane = tid & 31, warp = tid >> 5;
    int wm = (warp & 3) * 32;
    int wn = (warp >> 2) * 64;
    int r0 = blockIdx.x * BM, c0 = blockIdx.y * BN;

    float acc[2][8][4];
#pragma unroll
    for (int mi = 0; mi < 2; mi++)
#pragma unroll
        for (int ni = 0; ni < 8; ni++)
#pragma unroll
            for (int j = 0; j < 4; j++) acc[mi][ni][j] = 0.f;

    int arow = tid & 127;
    int ak4  = (tid >> 7) * 8;

    for (int k0 = 0; k0 < FD; k0 += BK) {
        int gr = r0 + arow;
        float4 av0, av1;
        if (gr < n) {
            const float4* p = (const float4*)(A + (size_t)gr * FD + k0 + ak4);
            av0 = p[0]; av1 = p[1];
        } else {
            av0 = make_float4(0, 0, 0, 0); av1 = av0;
        }
        As[ak4 + 0][arow] = f2tf32(av0.x);
        As[ak4 + 1][arow] = f2tf32(av0.y);
        As[ak4 + 2][arow] = f2tf32(av0.z);
        As[ak4 + 3][arow] = f2tf32(av0.w);
        As[ak4 + 4][arow] = f2tf32(av1.x);
        As[ak4 + 5][arow] = f2tf32(av1.y);
        As[ak4 + 6][arow] = f2tf32(av1.z);
        As[ak4 + 7][arow] = f2tf32(av1.w);

#pragma unroll
        for (int rep = 0; rep < 2; rep++) {
            int i = tid + rep * 256;
            int bk = i >> 5, bc = (i & 31) * 4;
            float4 bv = *(const float4*)(B + (size_t)(k0 + bk) * FD + c0 + bc);
            Bs[bk][bc + 0] = f2tf32(bv.x);
            Bs[bk][bc + 1] = f2tf32(bv.y);
            Bs[bk][bc + 2] = f2tf32(bv.z);
            Bs[bk][bc + 3] = f2tf32(bv.w);
        }
        __syncthreads();

#pragma unroll
        for (int ks = 0; ks < BK; ks += 8) {
            uint32_t afr[2][4], bfr[8][2];
            int krow = ks + (lane & 3);
            int grp  = lane >> 2;
#pragma unroll
            for (int mi = 0; mi < 2; mi++) {
                int row = wm + mi * 16 + grp;
                afr[mi][0] = As[krow][row];
                afr[mi][1] = As[krow][row + 8];
                afr[mi][2] = As[krow + 4][row];
                afr[mi][3] = As[krow + 4][row + 8];
            }
#pragma unroll
            for (int ni = 0; ni < 8; ni++) {
                int col = wn + ni * 8 + grp;
                bfr[ni][0] = Bs[krow][col];
                bfr[ni][1] = Bs[krow + 4][col];
            }
#pragma unroll
            for (int mi = 0; mi < 2; mi++)
#pragma unroll
                for (int ni = 0; ni < 8; ni++)
                    mma_tf32(acc[mi][ni], afr[mi], bfr[ni]);
        }
        __syncthreads();
    }

    int grp = lane >> 2;
#pragma unroll
    for (int mi = 0; mi < 2; mi++) {
        int row = r0 + wm + mi * 16 + grp;
#pragma unroll
        for (int ni = 0; ni < 8; ni++) {
            int col = c0 + wn + ni * 8 + (lane & 3) * 2;
            float bb0 = bias[col], bb1 = bias[col + 1];
            if (row < n) {
                float2 v;
                v.x = fmaxf(acc[mi][ni][0] + bb0, 0.f);
                v.y = fmaxf(acc[mi][ni][1] + bb1, 0.f);
                *(float2*)(g_t + (size_t)row * FD + col) = v;
            }
            if (row + 8 < n) {
                float2 v;
                v.x = fmaxf(acc[mi][ni][2] + bb0, 0.f);
                v.y = fmaxf(acc[mi][ni][3] + bb1, 0.f);
                *(float2*)(g_t + (size_t)(row + 8) * FD + col) = v;
            }
        }
    }
}

// ---------------- build WrAll [512,120] = [Wa | Wb | Wc] (tf32 bits) ----------------
// Wa = W2[0:512]+W2[512:1024], Wb = W2[1024:1536]+W2[1536:2048], Wc = W2[2048:2560]
__global__ void k_buildwr(const float* __restrict__ W2) {
    int idx = blockIdx.x * blockDim.x + threadIdx.x;
    if (idx >= FD * NCOL) return;
    int k = idx / NCOL, c = idx % NCOL;
    float v;
    if (c < 40)       v = W2[k * NC + c]           + W2[(k + 512) * NC + c];
    else if (c < 80)  v = W2[(k + 1024) * NC + c - 40] + W2[(k + 1536) * NC + c - 40];
    else              v = W2[(k + 2048) * NC + c - 80];
    g_wrall[idx] = f2tf32(v);
}

// ---------------- TF32 GEMM2a: P = t @ WrAll  [n,512]x[512,120] ----------------
// 128 rows/block, 256 thr (8 warps, warp w owns rows w*16..+15)
__global__ __launch_bounds__(256) void k_gemm2a(int n) {
    __shared__ uint32_t As[16][132];
    __shared__ uint32_t Ws[16][NCOL];

    int tid  = threadIdx.x;
    int lane = tid & 31, warp = tid >> 5;
    int r0   = blockIdx.x * 128;

    float acc[15][4];
#pragma unroll
    for (int t = 0; t < 15; t++)
#pragma unroll
        for (int j = 0; j < 4; j++) acc[t][j] = 0.f;

    int arow = tid & 127;
    int ak   = (tid >> 7) * 8;

    for (int kt = 0; kt < FD; kt += 16) {
        {
            int gr = r0 + arow;
            float4 v0, v1;
            if (gr < n) {
                const float4* p = (const float4*)(g_t + (size_t)gr * FD + kt + ak);
                v0 = p[0]; v1 = p[1];
            } else {
                v0 = make_float4(0, 0, 0, 0); v1 = v0;
            }
            As[ak + 0][arow] = f2tf32(v0.x);
            As[ak + 1][arow] = f2tf32(v0.y);
            As[ak + 2][arow] = f2tf32(v0.z);
            As[ak + 3][arow] = f2tf32(v0.w);
            As[ak + 4][arow] = f2tf32(v1.x);
            As[ak + 5][arow] = f2tf32(v1.y);
            As[ak + 6][arow] = f2tf32(v1.z);
            As[ak + 7][arow] = f2tf32(v1.w);
        }
        for (int idx = tid; idx < 16 * NCOL; idx += 256) {
            int kk = idx / NCOL, c = idx % NCOL;
            Ws[kk][c] = g_wrall[(kt + kk) * NCOL + c];
        }
        __syncthreads();

#pragma unroll
        for (int ks = 0; ks < 16; ks += 8) {
            int krow = ks + (lane & 3);
            int grp  = lane >> 2;
            uint32_t a[4];
            int row = warp * 16 + grp;
            a[0] = As[krow][row];
            a[1] = As[krow][row + 8];
            a[2] = As[krow + 4][row];
            a[3] = As[krow + 4][row + 8];
#pragma unroll
            for (int t = 0; t < 15; t++) {
                uint32_t b[2];
                int col = t * 8 + grp;
                b[0] = Ws[krow][col];
                b[1] = Ws[krow + 4][col];
                mma_tf32(acc[t], a, b);
            }
        }
        __syncthreads();
    }

    // epilogue: cols 0..39 -> g_p0 (stride 40), cols 40..119 -> g_p12 (stride 80)
    int grp = lane >> 2, q = lane & 3;
    int rlo = r0 + warp * 16 + grp;
    int rhi = rlo + 8;
#pragma unroll
    for (int t = 0; t < 15; t++) {
        int c = t * 8 + q * 2;
        if (rlo < n) {
            float2 v = make_float2(acc[t][0], acc[t][1]);
            if (c < 40) *(float2*)(g_p0  + (size_t)rlo * 40 + c)      = v;
            else        *(float2*)(g_p12 + (size_t)rlo * 80 + c - 40) = v;
        }
        if (rhi < n) {
            float2 v = make_float2(acc[t][2], acc[t][3]);
            if (c < 40) *(float2*)(g_p0  + (size_t)rhi * 40 + c)      = v;
            else        *(float2*)(g_p12 + (size_t)rhi * 80 + c - 40) = v;
        }
    }
}

// ---------------- SpMM-A: Q12 = Ahat @ P12  (80-wide, warp per node) ----------------
__global__ __launch_bounds__(256) void k_spmmA(int n) {
    int node = blockIdx.x * 8 + (threadIdx.x >> 5);
    int lane = threadIdx.x & 31;
    if (node >= n) return;

    float di = g_dinv[node];
    const float4* P = (const float4*)g_p12;   // row stride 20 float4
    float4 acc = make_float4(0, 0, 0, 0);
    if (lane < 20) {
        float4 s = P[(size_t)node * 20 + lane];
        float w = di * di;
        acc.x = s.x * w; acc.y = s.y * w; acc.z = s.z * w; acc.w = s.w * w;
    }

    int beg = g_rowptr[node], end = g_rowptr[node + 1];
    for (int b = beg; b < end; b += 32) {
        int m = end - b; if (m > 32) m = 32;
        int c = 0; float w = 0.f;
        if (lane < m) { c = g_csrcol[b + lane]; w = di * g_dinv[c]; }
        int jj = 0;
        for (; jj + 4 <= m; jj += 4) {
            int   c0 = __shfl_sync(0xffffffffu, c, jj);
            int   c1 = __shfl_sync(0xffffffffu, c, jj + 1);
            int   c2 = __shfl_sync(0xffffffffu, c, jj + 2);
            int   c3 = __shfl_sync(0xffffffffu, c, jj + 3);
            float w0 = __shfl_sync(0xffffffffu, w, jj);
            float w1 = __shfl_sync(0xffffffffu, w, jj + 1);
            float w2 = __shfl_sync(0xffffffffu, w, jj + 2);
            float w3 = __shfl_sync(0xffffffffu, w, jj + 3);
            if (lane < 20) {
                float4 v0 = P[(size_t)c0 * 20 + lane];
                float4 v1 = P[(size_t)c1 * 20 + lane];
                float4 v2 = P[(size_t)c2 * 20 + lane];
                float4 v3 = P[(size_t)c3 * 20 + lane];
                acc.x += w0 * v0.x; acc.y += w0 * v0.y; acc.z += w0 * v0.z; acc.w += w0 * v0.w;
                acc.x += w1 * v1.x; acc.y += w1 * v1.y; acc.z += w1 * v1.z; acc.w += w1 * v1.w;
                acc.x += w2 * v2.x; acc.y += w2 * v2.y; acc.z += w2 * v2.z; acc.w += w2 * v2.w;
                acc.x += w3 * v3.x; acc.y += w3 * v3.y; acc.z += w3 * v3.z; acc.w += w3 * v3.w;
            }
        }
        for (; jj < m; jj++) {
            int   cc = __shfl_sync(0xffffffffu, c, jj);
            float ww = __shfl_sync(0xffffffffu, w, jj);
            if (lane < 20) {
                float4 v = P[(size_t)cc * 20 + lane];
                acc.x += ww * v.x; acc.y += ww * v.y; acc.z += ww * v.z; acc.w += ww * v.w;
            }
        }
    }
    if (lane < 20) ((float4*)g_q12)[(size_t)node * 20 + lane] = acc;
}

// ---------------- SpMM-B: R = Ahat @ Q2  (40-wide; Q2 = cols 40..79 of Q12) ----------------
__global__ __launch_bounds__(256) void k_spmmB(int n) {
    int node = blockIdx.x * 8 + (threadIdx.x >> 5);
    int lane = threadIdx.x & 31;
    if (node >= n) return;

    float di = g_dinv[node];
    const float4* Q = (const float4*)g_q12;   // row stride 20; Q2 at offset +10
    float4 acc = make_float4(0, 0, 0, 0);
    if (lane < 10) {
        float4 s = Q[(size_t)node * 20 + 10 + lane];
        float w = di * di;
        acc.x = s.x * w; acc.y = s.y * w; acc.z = s.z * w; acc.w = s.w * w;
    }

    int beg = g_rowptr[node], end = g_rowptr[node + 1];
    for (int b = beg; b < end; b += 32) {
        int m = end - b; if (m > 32) m = 32;
        int c = 0; float w = 0.f;
        if (lane < m) { c = g_csrcol[b + lane]; w = di * g_dinv[c]; }
        int jj = 0;
        for (; jj + 4 <= m; jj += 4) {
            int   c0 = __shfl_sync(0xffffffffu, c, jj);
            int   c1 = __shfl_sync(0xffffffffu, c, jj + 1);
            int   c2 = __shfl_sync(0xffffffffu, c, jj + 2);
            int   c3 = __shfl_sync(0xffffffffu, c, jj + 3);
            float w0 = __shfl_sync(0xffffffffu, w, jj);
            float w1 = __shfl_sync(0xffffffffu, w, jj + 1);
            float w2 = __shfl_sync(0xffffffffu, w, jj + 2);
            float w3 = __shfl_sync(0xffffffffu, w, jj + 3);
            if (lane < 10) {
                float4 v0 = Q[(size_t)c0 * 20 + 10 + lane];
                float4 v1 = Q[(size_t)c1 * 20 + 10 + lane];
                float4 v2 = Q[(size_t)c2 * 20 + 10 + lane];
                float4 v3 = Q[(size_t)c3 * 20 + 10 + lane];
                acc.x += w0 * v0.x; acc.y += w0 * v0.y; acc.z += w0 * v0.z; acc.w += w0 * v0.w;
                acc.x += w1 * v1.x; acc.y += w1 * v1.y; acc.z += w1 * v1.z; acc.w += w1 * v1.w;
                acc.x += w2 * v2.x; acc.y += w2 * v2.y; acc.z += w2 * v2.z; acc.w += w2 * v2.w;
                acc.x += w3 * v3.x; acc.y += w3 * v3.y; acc.z += w3 * v3.z; acc.w += w3 * v3.w;
            }
        }
        for (; jj < m; jj++) {
            int   cc = __shfl_sync(0xffffffffu, c, jj);
            float ww = __shfl_sync(0xffffffffu, w, jj);
            if (lane < 10) {
                float4 v = Q[(size_t)cc * 20 + 10 + lane];
                acc.x += ww * v.x; acc.y += ww * v.y; acc.z += ww * v.z; acc.w += ww * v.w;
            }
        }
    }
    if (lane < 10) ((float4*)g_r)[(size_t)node * 10 + lane] = acc;
}

// ---------------- final: out = log_softmax(P0 + Q1 + R + b2), warp per row ----------------
__global__ __launch_bounds__(256) void k_final(const float* __restrict__ b2,
                                               float* __restrict__ out, int n) {
    int node = blockIdx.x * 8 + (threadIdx.x >> 5);
    int lane = threadIdx.x & 31;
    if (node >= n) return;

    float2 v = make_float2(0.f, 0.f);
    if (lane < 20) {
        float2 a = ((const float2*)g_p0) [(size_t)node * 20 + lane];
        float2 b = ((const float2*)g_q12)[(size_t)node * 40 + lane];   // Q1 = first 40 floats
        float2 r = ((const float2*)g_r)  [(size_t)node * 20 + lane];
        float2 bb = ((const float2*)b2)[lane];
        v.x = a.x + b.x + r.x + bb.x;
        v.y = a.y + b.y + r.y + bb.y;
    }

    float m = (lane < 20) ? fmaxf(v.x, v.y) : -1e30f;
#pragma unroll
    for (int o = 16; o > 0; o >>= 1) m = fmaxf(m, __shfl_xor_sync(0xffffffffu, m, o));
    float s = (lane < 20) ? (expf(v.x - m) + expf(v.y - m)) : 0.f;
#pragma unroll
    for (int o = 16; o > 0; o >>= 1) s += __shfl_xor_sync(0xffffffffu, s, o);
    float z = m + logf(s);

    if (lane < 20) {
        float2 o2 = make_float2(v.x - z, v.y - z);
        *(float2*)(out + (size_t)node * NC + lane * 2) = o2;
    }
}

// ---------------- launch ----------------
extern "C" void kernel_launch(void* const* d_in, const int* in_sizes, int n_in,
                              void* d_out, int out_size) {
    const float* x    = (const float*)d_in[0];
    const int*   erow = (const int*)  d_in[1];
    const int*   ecol = (const int*)  d_in[2];
    const float* W1   = (const float*)d_in[3];
    const float* b1   = (const float*)d_in[4];
    const float* W2   = (const float*)d_in[5];
    const float* b2   = (const float*)d_in[6];
    float* out = (float*)d_out;

    int n = in_sizes[0] / FD;   // 50000
    int e = in_sizes[1];        // 1600000
    (void)n_in; (void)out_size;

    int nb = (n + 1023) / 1024;
    int nwb = (n + 7) / 8;      // warp-per-node blocks

    // 1) degree / dinv / CSR build
    k_init   <<<(n + 255) / 256, 256>>>(n);
    k_count  <<<(e + 255) / 256, 256>>>(erow, ecol, e);
    k_dinv   <<<(n + 255) / 256, 256>>>(n);
    k_scan1  <<<nb, 256>>>(n);
    k_scan2  <<<1, 1>>>(nb, n);
    k_scan3  <<<nb, 256>>>(n);
    k_scatter<<<(e + 255) / 256, 256>>>(erow, ecol, e);

    // 2) t = relu(x @ W1 + b1)
    dim3 g1((n + 127) / 128, FD / 128);
    k_gemm1<<<g1, 256>>>(x, W1, b1, n);

    // 3) P = t @ [Wa|Wb|Wc]
    k_buildwr<<<(FD * NCOL + 255) / 256, 256>>>(W2);
    k_gemm2a<<<(n + 127) / 128, 256>>>(n);

    // 4) Q12 = Ahat P12 ; R = Ahat Q2
    k_spmmA<<<nwb, 256>>>(n);
    k_spmmB<<<nwb, 256>>>(n);

    // 5) out = log_softmax(P0 + Q1 + R + b2)
    k_final<<<nwb, 256>>>(b2, out, n);
}

// round 9
// speedup vs baseline: 3.1173x; 1.4189x over previous
#include <cuda_runtime.h>
#include <cuda_bf16.h>
#include <math.h>
#include <stdint.h>

#define NN 50000
#define EE 1600000
#define FD 512
#define NC 40
#define NCOL 120   // [Wa|Wb|Wc] columns

// ---------------- device scratch ----------------
__device__ float g_deg[NN];
__device__ float g_dinv[NN];
__device__ __align__(16) int g_cnt[NN];
__device__ int   g_fill[NN];
__device__ int   g_rowptr[NN + 1];
__device__ int   g_csrcol[EE];
__device__ int   g_bsum[64];
__device__ __align__(16) float g_t  [(size_t)NN * FD];   // relu(xW1+b1)
__device__ __align__(16) float g_p0 [(size_t)NN * 40];   // t*Wa
__device__ __align__(16) float g_p12[(size_t)NN * 80];   // [t*Wb | t*Wc]
__device__ __align__(16) float g_q12[(size_t)NN * 80];   // [A p1 | A p2]
__device__ __align__(16) float g_r  [(size_t)NN * 40];   // A^2 p2
__device__ uint32_t g_wrall[FD * NCOL];                  // tf32 bits
__device__ __align__(16) __nv_bfloat16 g_w1t[FD * FD];   // W1 transposed, bf16 [n][k]

// ---------------- preprocessing ----------------
__global__ void k_init(int n) {
    int i = blockIdx.x * blockDim.x + threadIdx.x;
    if (i < n) { g_deg[i] = 1.0f; g_cnt[i] = 0; g_fill[i] = 0; }
}

__global__ void k_count(const int* __restrict__ row, const int* __restrict__ col, int e) {
    int i = blockIdx.x * blockDim.x + threadIdx.x;
    if (i < e) {
        atomicAdd(&g_deg[col[i]], 1.0f);
        atomicAdd(&g_cnt[row[i]], 1);
    }
}

__global__ void k_dinv(int n) {
    int i = blockIdx.x * blockDim.x + threadIdx.x;
    if (i < n) g_dinv[i] = rsqrtf(g_deg[i]);
}

__global__ void k_scan1(int n) {
    __shared__ int sh[256];
    int b = blockIdx.x, t = threadIdx.x;
    int i = b * 1024 + t * 4;
    int s = 0;
    if (i + 3 < n) { int4 v = *(const int4*)(g_cnt + i); s = v.x + v.y + v.z + v.w; }
    else { for (int j = 0; j < 4; j++) if (i + j < n) s += g_cnt[i + j]; }
    sh[t] = s; __syncthreads();
    for (int o = 128; o > 0; o >>= 1) { if (t < o) sh[t] += sh[t + o]; __syncthreads(); }
    if (t == 0) g_bsum[b] = sh[0];
}

__global__ void k_scan2(int nb, int n) {
    int run = 0;
    for (int b = 0; b < nb; b++) { int v = g_bsum[b]; g_bsum[b] = run; run += v; }
    g_rowptr[n] = run;
}

__global__ void k_scan3(int n) {
    __shared__ int sh[256];
    int b = blockIdx.x, t = threadIdx.x;
    int i = b * 1024 + t * 4;
    int c0 = 0, c1 = 0, c2 = 0, c3 = 0;
    if (i + 3 < n) { int4 v = *(const int4*)(g_cnt + i); c0 = v.x; c1 = v.y; c2 = v.z; c3 = v.w; }
    else {
        if (i     < n) c0 = g_cnt[i];
        if (i + 1 < n) c1 = g_cnt[i + 1];
        if (i + 2 < n) c2 = g_cnt[i + 2];
        if (i + 3 < n) c3 = g_cnt[i + 3];
    }
    int s = c0 + c1 + c2 + c3;
    sh[t] = s; __syncthreads();
    for (int o = 1; o < 256; o <<= 1) {
        int v = (t >= o) ? sh[t - o] : 0;
        __syncthreads();
        sh[t] += v;
        __syncthreads();
    }
    int base = g_bsum[b] + ((t > 0) ? sh[t - 1] : 0);
    if (i     < n) { g_rowptr[i]     = base; base += c0; }
    if (i + 1 < n) { g_rowptr[i + 1] = base; base += c1; }
    if (i + 2 < n) { g_rowptr[i + 2] = base; base += c2; }
    if (i + 3 < n) { g_rowptr[i + 3] = base; }
}

__global__ void k_scatter(const int* __restrict__ row, const int* __restrict__ col, int e) {
    int i = blockIdx.x * blockDim.x + threadIdx.x;
    if (i < e) {
        int r = row[i];
        int pos = g_rowptr[r] + atomicAdd(&g_fill[r], 1);
        g_csrcol[pos] = col[i];
    }
}

// ---------------- W1 transpose -> bf16 [n][k] ----------------
__global__ void k_w1t(const float* __restrict__ W1) {
    __shared__ float tile[32][33];
    int bx = blockIdx.x * 32, by = blockIdx.y * 32;
    int tx = threadIdx.x, ty = threadIdx.y;
#pragma unroll
    for (int i = 0; i < 4; i++)
        tile[ty + i * 8][tx] = W1[(size_t)(by + ty + i * 8) * FD + bx + tx];
    __syncthreads();
#pragma unroll
    for (int i = 0; i < 4; i++)
        g_w1t[(size_t)(bx + ty + i * 8) * FD + by + tx] =
            __float2bfloat16(tile[tx][ty + i * 8]);
}

// ---------------- bf16 HMMA GEMM1: t = relu(x @ W1 + b1) ----------------
__device__ __forceinline__ void mma_bf16(float* d, const uint32_t* a, const uint32_t* b) {
    asm volatile(
        "mma.sync.aligned.m16n8k16.row.col.f32.bf16.bf16.f32 "
        "{%0,%1,%2,%3}, {%4,%5,%6,%7}, {%8,%9}, {%0,%1,%2,%3};\n"
        : "+f"(d[0]), "+f"(d[1]), "+f"(d[2]), "+f"(d[3])
        : "r"(a[0]), "r"(a[1]), "r"(a[2]), "r"(a[3]), "r"(b[0]), "r"(b[1]));
}

#define BM 128
#define BN 128
#define BK 32
#define ASTR 40   // bf16 row stride (32 data + 8 pad) -> conflict-free fragment loads

__global__ __launch_bounds__(256, 2) void k_gemm1(const float* __restrict__ A,
                                                  const float* __restrict__ bias, int n) {
    __shared__ __nv_bfloat16 As[BM * ASTR];
    __shared__ __nv_bfloat16 Bs[BN * ASTR];
    int tid = threadIdx.x;
    int lane = tid & 31, warp = tid >> 5;
    int wm = (warp & 3) * 32;   // warp row offset
    int wn = (warp >> 2) * 64;  // warp col offset
    int r0 = blockIdx.x * BM, c0 = blockIdx.y * BN;

    float acc[2][8][4];
#pragma unroll
    for (int mi = 0; mi < 2; mi++)
#pragma unroll
        for (int ni = 0; ni < 8; ni++)
#pragma unroll
            for (int j = 0; j < 4; j++) acc[mi][ni][j] = 0.f;

    for (int k0 = 0; k0 < FD; k0 += BK) {
        // A tile: 128 rows x 32 cols fp32 -> bf16, As[m][k]
#pragma unroll
        for (int it = 0; it < 4; it++) {
            int idx = tid + it * 256;      // 0..1023 float4 slots
            int row = idx >> 3;            // 8 float4 per row
            int q   = idx & 7;
            int gr  = r0 + row;
            float4 v = (gr < n) ? *(const float4*)(A + (size_t)gr * FD + k0 + q * 4)
                                : make_float4(0.f, 0.f, 0.f, 0.f);
            __nv_bfloat162 p0 = __floats2bfloat162_rn(v.x, v.y);
            __nv_bfloat162 p1 = __floats2bfloat162_rn(v.z, v.w);
            *(uint2*)(As + row * ASTR + q * 4) = make_uint2(*(uint32_t*)&p0, *(uint32_t*)&p1);
        }
        // B tile: 128 n-rows x 32 k-cols bf16 copy from g_w1t
#pragma unroll
        for (int it = 0; it < 2; it++) {
            int idx = tid + it * 256;      // 0..511 uint4 slots
            int row = idx >> 2;            // 4 uint4 per row
            int q   = idx & 3;
            uint4 v = *(const uint4*)(g_w1t + (size_t)(c0 + row) * FD + k0 + q * 8);
            *(uint4*)(Bs + row * ASTR + q * 8) = v;
        }
        __syncthreads();

        int g = lane >> 2, q = lane & 3;
#pragma unroll
        for (int ks = 0; ks < 2; ks++) {
            uint32_t afr[2][4], bfr[8][2];
#pragma unroll
            for (int mi = 0; mi < 2; mi++) {
                const __nv_bfloat16* base = As + (wm + mi * 16 + g) * ASTR + ks * 16 + q * 2;
                afr[mi][0] = *(const uint32_t*)(base);
                afr[mi][1] = *(const uint32_t*)(base + 8 * ASTR);
                afr[mi][2] = *(const uint32_t*)(base + 8);
                afr[mi][3] = *(const uint32_t*)(base + 8 * ASTR + 8);
            }
#pragma unroll
            for (int ni = 0; ni < 8; ni++) {
                const __nv_bfloat16* base = Bs + (wn + ni * 8 + g) * ASTR + ks * 16 + q * 2;
                bfr[ni][0] = *(const uint32_t*)(base);
                bfr[ni][1] = *(const uint32_t*)(base + 8);
            }
#pragma unroll
            for (int mi = 0; mi < 2; mi++)
#pragma unroll
                for (int ni = 0; ni < 8; ni++)
                    mma_bf16(acc[mi][ni], afr[mi], bfr[ni]);
        }
        __syncthreads();
    }

    // epilogue: bias + relu -> g_t
    int g = lane >> 2, q = lane & 3;
#pragma unroll
    for (int mi = 0; mi < 2; mi++) {
        int row = r0 + wm + mi * 16 + g;
#pragma unroll
        for (int ni = 0; ni < 8; ni++) {
            int col = c0 + wn + ni * 8 + q * 2;
            float bb0 = bias[col], bb1 = bias[col + 1];
            if (row < n) {
                float2 v;
                v.x = fmaxf(acc[mi][ni][0] + bb0, 0.f);
                v.y = fmaxf(acc[mi][ni][1] + bb1, 0.f);
                *(float2*)(g_t + (size_t)row * FD + col) = v;
            }
            if (row + 8 < n) {
                float2 v;
                v.x = fmaxf(acc[mi][ni][2] + bb0, 0.f);
                v.y = fmaxf(acc[mi][ni][3] + bb1, 0.f);
                *(float2*)(g_t + (size_t)(row + 8) * FD + col) = v;
            }
        }
    }
}

// ---------------- TF32 helpers ----------------
__device__ __forceinline__ uint32_t f2tf32(float f) {
    uint32_t u;
    asm("cvt.rna.tf32.f32 %0, %1;" : "=r"(u) : "f"(f));
    return u;
}

__device__ __forceinline__ void mma_tf32(float* d, const uint32_t* a, const uint32_t* b) {
    asm volatile(
        "mma.sync.aligned.m16n8k8.row.col.f32.tf32.tf32.f32 "
        "{%0,%1,%2,%3}, {%4,%5,%6,%7}, {%8,%9}, {%0,%1,%2,%3};\n"
        : "+f"(d[0]), "+f"(d[1]), "+f"(d[2]), "+f"(d[3])
        : "r"(a[0]), "r"(a[1]), "r"(a[2]), "r"(a[3]), "r"(b[0]), "r"(b[1]));
}

// ---------------- build WrAll [512,120] = [Wa | Wb | Wc] (tf32 bits) ----------------
__global__ void k_buildwr(const float* __restrict__ W2) {
    int idx = blockIdx.x * blockDim.x + threadIdx.x;
    if (idx >= FD * NCOL) return;
    int k = idx / NCOL, c = idx % NCOL;
    float v;
    if (c < 40)       v = W2[k * NC + c]           + W2[(k + 512) * NC + c];
    else if (c < 80)  v = W2[(k + 1024) * NC + c - 40] + W2[(k + 1536) * NC + c - 40];
    else              v = W2[(k + 2048) * NC + c - 80];
    g_wrall[idx] = f2tf32(v);
}

// ---------------- TF32 GEMM2a: P = t @ WrAll  [n,512]x[512,120] ----------------
__global__ __launch_bounds__(256) void k_gemm2a(int n) {
    __shared__ uint32_t As[16][132];
    __shared__ uint32_t Ws[16][NCOL];

    int tid  = threadIdx.x;
    int lane = tid & 31, warp = tid >> 5;
    int r0   = blockIdx.x * 128;

    float acc[15][4];
#pragma unroll
    for (int t = 0; t < 15; t++)
#pragma unroll
        for (int j = 0; j < 4; j++) acc[t][j] = 0.f;

    int arow = tid & 127;
    int ak   = (tid >> 7) * 8;

    for (int kt = 0; kt < FD; kt += 16) {
        {
            int gr = r0 + arow;
            float4 v0, v1;
            if (gr < n) {
                const float4* p = (const float4*)(g_t + (size_t)gr * FD + kt + ak);
                v0 = p[0]; v1 = p[1];
            } else {
                v0 = make_float4(0, 0, 0, 0); v1 = v0;
            }
            As[ak + 0][arow] = f2tf32(v0.x);
            As[ak + 1][arow] = f2tf32(v0.y);
            As[ak + 2][arow] = f2tf32(v0.z);
            As[ak + 3][arow] = f2tf32(v0.w);
            As[ak + 4][arow] = f2tf32(v1.x);
            As[ak + 5][arow] = f2tf32(v1.y);
            As[ak + 6][arow] = f2tf32(v1.z);
            As[ak + 7][arow] = f2tf32(v1.w);
        }
        for (int idx = tid; idx < 16 * NCOL; idx += 256) {
            int kk = idx / NCOL, c = idx % NCOL;
            Ws[kk][c] = g_wrall[(kt + kk) * NCOL + c];
        }
        __syncthreads();

#pragma unroll
        for (int ks = 0; ks < 16; ks += 8) {
            int krow = ks + (lane & 3);
            int grp  = lane >> 2;
            uint32_t a[4];
            int row = warp * 16 + grp;
            a[0] = As[krow][row];
            a[1] = As[krow][row + 8];
            a[2] = As[krow + 4][row];
            a[3] = As[krow + 4][row + 8];
#pragma unroll
            for (int t = 0; t < 15; t++) {
                uint32_t b[2];
                int col = t * 8 + grp;
                b[0] = Ws[krow][col];
                b[1] = Ws[krow + 4][col];
                mma_tf32(acc[t], a, b);
            }
        }
        __syncthreads();
    }

    int grp = lane >> 2, q = lane & 3;
    int rlo = r0 + warp * 16 + grp;
    int rhi = rlo + 8;
#pragma unroll
    for (int t = 0; t < 15; t++) {
        int c = t * 8 + q * 2;
        if (rlo < n) {
            float2 v = make_float2(acc[t][0], acc[t][1]);
            if (c < 40) *(float2*)(g_p0  + (size_t)rlo * 40 + c)      = v;
            else        *(float2*)(g_p12 + (size_t)rlo * 80 + c - 40) = v;
        }
        if (rhi < n) {
            float2 v = make_float2(acc[t][2], acc[t][3]);
            if (c < 40) *(float2*)(g_p0  + (size_t)rhi * 40 + c)      = v;
            else        *(float2*)(g_p12 + (size_t)rhi * 80 + c - 40) = v;
        }
    }
}

// ---------------- SpMM-A: Q12 = Ahat @ P12  (80-wide, warp per node) ----------------
__global__ __launch_bounds__(256) void k_spmmA(int n) {
    int node = blockIdx.x * 8 + (threadIdx.x >> 5);
    int lane = threadIdx.x & 31;
    if (node >= n) return;

    float di = g_dinv[node];
    const float4* P = (const float4*)g_p12;
    float4 acc = make_float4(0, 0, 0, 0);
    if (lane < 20) {
        float4 s = P[(size_t)node * 20 + lane];
        float w = di * di;
        acc.x = s.x * w; acc.y = s.y * w; acc.z = s.z * w; acc.w = s.w * w;
    }

    int beg = g_rowptr[node], end = g_rowptr[node + 1];
    for (int b = beg; b < end; b += 32) {
        int m = end - b; if (m > 32) m = 32;
        int c = 0; float w = 0.f;
        if (lane < m) { c = g_csrcol[b + lane]; w = di * g_dinv[c]; }
        int jj = 0;
        for (; jj + 4 <= m; jj += 4) {
            int   c0 = __shfl_sync(0xffffffffu, c, jj);
            int   c1 = __shfl_sync(0xffffffffu, c, jj + 1);
            int   c2 = __shfl_sync(0xffffffffu, c, jj + 2);
            int   c3 = __shfl_sync(0xffffffffu, c, jj + 3);
            float w0 = __shfl_sync(0xffffffffu, w, jj);
            float w1 = __shfl_sync(0xffffffffu, w, jj + 1);
            float w2 = __shfl_sync(0xffffffffu, w, jj + 2);
            float w3 = __shfl_sync(0xffffffffu, w, jj + 3);
            if (lane < 20) {
                float4 v0 = P[(size_t)c0 * 20 + lane];
                float4 v1 = P[(size_t)c1 * 20 + lane];
                float4 v2 = P[(size_t)c2 * 20 + lane];
                float4 v3 = P[(size_t)c3 * 20 + lane];
                acc.x += w0 * v0.x; acc.y += w0 * v0.y; acc.z += w0 * v0.z; acc.w += w0 * v0.w;
                acc.x += w1 * v1.x; acc.y += w1 * v1.y; acc.z += w1 * v1.z; acc.w += w1 * v1.w;
                acc.x += w2 * v2.x; acc.y += w2 * v2.y; acc.z += w2 * v2.z; acc.w += w2 * v2.w;
                acc.x += w3 * v3.x; acc.y += w3 * v3.y; acc.z += w3 * v3.z; acc.w += w3 * v3.w;
            }
        }
        for (; jj < m; jj++) {
            int   cc = __shfl_sync(0xffffffffu, c, jj);
            float ww = __shfl_sync(0xffffffffu, w, jj);
            if (lane < 20) {
                float4 v = P[(size_t)cc * 20 + lane];
                acc.x += ww * v.x; acc.y += ww * v.y; acc.z += ww * v.z; acc.w += ww * v.w;
            }
        }
    }
    if (lane < 20) ((float4*)g_q12)[(size_t)node * 20 + lane] = acc;
}

// ---------------- SpMM-B: R = Ahat @ Q2  (40-wide) ----------------
__global__ __launch_bounds__(256) void k_spmmB(int n) {
    int node = blockIdx.x * 8 + (threadIdx.x >> 5);
    int lane = threadIdx.x & 31;
    if (node >= n) return;

    float di = g_dinv[node];
    const float4* Q = (const float4*)g_q12;
    float4 acc = make_float4(0, 0, 0, 0);
    if (lane < 10) {
        float4 s = Q[(size_t)node * 20 + 10 + lane];
        float w = di * di;
        acc.x = s.x * w; acc.y = s.y * w; acc.z = s.z * w; acc.w = s.w * w;
    }

    int beg = g_rowptr[node], end = g_rowptr[node + 1];
    for (int b = beg; b < end; b += 32) {
        int m = end - b; if (m > 32) m = 32;
        int c = 0; float w = 0.f;
        if (lane < m) { c = g_csrcol[b + lane]; w = di * g_dinv[c]; }
        int jj = 0;
        for (; jj + 4 <= m; jj += 4) {
            int   c0 = __shfl_sync(0xffffffffu, c, jj);
            int   c1 = __shfl_sync(0xffffffffu, c, jj + 1);
            int   c2 = __shfl_sync(0xffffffffu, c, jj + 2);
            int   c3 = __shfl_sync(0xffffffffu, c, jj + 3);
            float w0 = __shfl_sync(0xffffffffu, w, jj);
            float w1 = __shfl_sync(0xffffffffu, w, jj + 1);
            float w2 = __shfl_sync(0xffffffffu, w, jj + 2);
            float w3 = __shfl_sync(0xffffffffu, w, jj + 3);
            if (lane < 10) {
                float4 v0 = Q[(size_t)c0 * 20 + 10 + lane];
                float4 v1 = Q[(size_t)c1 * 20 + 10 + lane];
                float4 v2 = Q[(size_t)c2 * 20 + 10 + lane];
                float4 v3 = Q[(size_t)c3 * 20 + 10 + lane];
                acc.x += w0 * v0.x; acc.y += w0 * v0.y; acc.z += w0 * v0.z; acc.w += w0 * v0.w;
                acc.x += w1 * v1.x; acc.y += w1 * v1.y; acc.z += w1 * v1.z; acc.w += w1 * v1.w;
                acc.x += w2 * v2.x; acc.y += w2 * v2.y; acc.z += w2 * v2.z; acc.w += w2 * v2.w;
                acc.x += w3 * v3.x; acc.y += w3 * v3.y; acc.z += w3 * v3.z; acc.w += w3 * v3.w;
            }
        }
        for (; jj < m; jj++) {
            int   cc = __shfl_sync(0xffffffffu, c, jj);
            float ww = __shfl_sync(0xffffffffu, w, jj);
            if (lane < 10) {
                float4 v = Q[(size_t)cc * 20 + 10 + lane];
                acc.x += ww * v.x; acc.y += ww * v.y; acc.z += ww * v.z; acc.w += ww * v.w;
            }
        }
    }
    if (lane < 10) ((float4*)g_r)[(size_t)node * 10 + lane] = acc;
}

// ---------------- final: out = log_softmax(P0 + Q1 + R + b2) ----------------
__global__ __launch_bounds__(256) void k_final(const float* __restrict__ b2,
                                               float* __restrict__ out, int n) {
    int node = blockIdx.x * 8 + (threadIdx.x >> 5);
    int lane = threadIdx.x & 31;
    if (node >= n) return;

    float2 v = make_float2(0.f, 0.f);
    if (lane < 20) {
        float2 a = ((const float2*)g_p0) [(size_t)node * 20 + lane];
        float2 b = ((const float2*)g_q12)[(size_t)node * 40 + lane];
        float2 r = ((const float2*)g_r)  [(size_t)node * 20 + lane];
        float2 bb = ((const float2*)b2)[lane];
        v.x = a.x + b.x + r.x + bb.x;
        v.y = a.y + b.y + r.y + bb.y;
    }

    float m = (lane < 20) ? fmaxf(v.x, v.y) : -1e30f;
#pragma unroll
    for (int o = 16; o > 0; o >>= 1) m = fmaxf(m, __shfl_xor_sync(0xffffffffu, m, o));
    float s = (lane < 20) ? (expf(v.x - m) + expf(v.y - m)) : 0.f;
#pragma unroll
    for (int o = 16; o > 0; o >>= 1) s += __shfl_xor_sync(0xffffffffu, s, o);
    float z = m + logf(s);

    if (lane < 20) {
        float2 o2 = make_float2(v.x - z, v.y - z);
        *(float2*)(out + (size_t)node * NC + lane * 2) = o2;
    }
}

// ---------------- launch ----------------
extern "C" void kernel_launch(void* const* d_in, const int* in_sizes, int n_in,
                              void* d_out, int out_size) {
    const float* x    = (const float*)d_in[0];
    const int*   erow = (const int*)  d_in[1];
    const int*   ecol = (const int*)  d_in[2];
    const float* W1   = (const float*)d_in[3];
    const float* b1   = (const float*)d_in[4];
    const float* W2   = (const float*)d_in[5];
    const float* b2   = (const float*)d_in[6];
    float* out = (float*)d_out;

    int n = in_sizes[0] / FD;   // 50000
    int e = in_sizes[1];        // 1600000
    (void)n_in; (void)out_size;

    int nb  = (n + 1023) / 1024;
    int nwb = (n + 7) / 8;

    // 1) degree / dinv / CSR build
    k_init   <<<(n + 255) / 256, 256>>>(n);
    k_count  <<<(e + 255) / 256, 256>>>(erow, ecol, e);
    k_dinv   <<<(n + 255) / 256, 256>>>(n);
    k_scan1  <<<nb, 256>>>(n);
    k_scan2  <<<1, 1>>>(nb, n);
    k_scan3  <<<nb, 256>>>(n);
    k_scatter<<<(e + 255) / 256, 256>>>(erow, ecol, e);

    // 2) t = relu(x @ W1 + b1)  [bf16 HMMA m16n8k16]
    k_w1t<<<dim3(16, 16), dim3(32, 8)>>>(W1);
    dim3 g1((n + 127) / 128, FD / 128);
    k_gemm1<<<g1, 256>>>(x, b1, n);

    // 3) P = t @ [Wa|Wb|Wc]
    k_buildwr<<<(FD * NCOL + 255) / 256, 256>>>(W2);
    k_gemm2a<<<(n + 127) / 128, 256>>>(n);

    // 4) Q12 = Ahat P12 ; R = Ahat Q2
    k_spmmA<<<nwb, 256>>>(n);
    k_spmmB<<<nwb, 256>>>(n);

    // 5) out = log_softmax(P0 + Q1 + R + b2)
    k_final<<<nwb, 256>>>(b2, out, n);
}

// round 11
// speedup vs baseline: 3.9383x; 1.2634x over previous
#include <cuda_runtime.h>
#include <cuda_bf16.h>
#include <math.h>
#include <stdint.h>

#define NN 50000
#define EE 1600000
#define FD 512
#define NC 40
#define NCOL 120   // [Wa|Wb|Wc] columns

// ---------------- device scratch ----------------
__device__ float g_deg[NN];
__device__ float g_dinv[NN];
__device__ __align__(16) int g_cnt[NN];
__device__ int   g_fill[NN];
__device__ int   g_rowptr[NN + 1];
__device__ int   g_csrcol[EE];
__device__ int   g_bsum[64];
__device__ __align__(16) __nv_bfloat16 g_tb[(size_t)NN * FD];  // relu(xW1+b1), bf16
__device__ __align__(16) float g_p0 [(size_t)NN * 40];   // t*Wa
__device__ __align__(16) float g_p12[(size_t)NN * 80];   // [t*Wb | t*Wc]
__device__ __align__(16) float g_q12[(size_t)NN * 80];   // [A p1 | A p2]
__device__ __align__(16) float g_r  [(size_t)NN * 40];   // A^2 p2
__device__ __align__(16) __nv_bfloat16 g_wrb[NCOL * FD]; // [Wa|Wb|Wc]^T bf16 [n][k]
__device__ __align__(16) __nv_bfloat16 g_w1t[FD * FD];   // W1 transposed, bf16 [n][k]

// ---------------- preprocessing ----------------
__global__ void k_init(int n) {
    int i = blockIdx.x * blockDim.x + threadIdx.x;
    if (i < n) { g_deg[i] = 1.0f; g_cnt[i] = 0; g_fill[i] = 0; }
}

__global__ void k_count(const int* __restrict__ row, const int* __restrict__ col, int e) {
    int i = blockIdx.x * blockDim.x + threadIdx.x;
    if (i < e) {
        atomicAdd(&g_deg[col[i]], 1.0f);
        atomicAdd(&g_cnt[row[i]], 1);
    }
}

// scan phase 1 + dinv fused (both depend only on k_count)
__global__ void k_scan1(int n) {
    __shared__ int sh[256];
    int b = blockIdx.x, t = threadIdx.x;
    int i = b * 1024 + t * 4;
    // dinv for this range
    for (int j = 0; j < 4; j++)
        if (i + j < n) g_dinv[i + j] = rsqrtf(g_deg[i + j]);
    int s = 0;
    if (i + 3 < n) { int4 v = *(const int4*)(g_cnt + i); s = v.x + v.y + v.z + v.w; }
    else { for (int j = 0; j < 4; j++) if (i + j < n) s += g_cnt[i + j]; }
    sh[t] = s; __syncthreads();
    for (int o = 128; o > 0; o >>= 1) { if (t < o) sh[t] += sh[t + o]; __syncthreads(); }
    if (t == 0) g_bsum[b] = sh[0];
}

__global__ void k_scan2(int nb, int n) {
    int run = 0;
    for (int b = 0; b < nb; b++) { int v = g_bsum[b]; g_bsum[b] = run; run += v; }
    g_rowptr[n] = run;
}

__global__ void k_scan3(int n) {
    __shared__ int sh[256];
    int b = blockIdx.x, t = threadIdx.x;
    int i = b * 1024 + t * 4;
    int c0 = 0, c1 = 0, c2 = 0, c3 = 0;
    if (i + 3 < n) { int4 v = *(const int4*)(g_cnt + i); c0 = v.x; c1 = v.y; c2 = v.z; c3 = v.w; }
    else {
        if (i     < n) c0 = g_cnt[i];
        if (i + 1 < n) c1 = g_cnt[i + 1];
        if (i + 2 < n) c2 = g_cnt[i + 2];
        if (i + 3 < n) c3 = g_cnt[i + 3];
    }
    int s = c0 + c1 + c2 + c3;
    sh[t] = s; __syncthreads();
    for (int o = 1; o < 256; o <<= 1) {
        int v = (t >= o) ? sh[t - o] : 0;
        __syncthreads();
        sh[t] += v;
        __syncthreads();
    }
    int base = g_bsum[b] + ((t > 0) ? sh[t - 1] : 0);
    if (i     < n) { g_rowptr[i]     = base; base += c0; }
    if (i + 1 < n) { g_rowptr[i + 1] = base; base += c1; }
    if (i + 2 < n) { g_rowptr[i + 2] = base; base += c2; }
    if (i + 3 < n) { g_rowptr[i + 3] = base; }
}

__global__ void k_scatter(const int* __restrict__ row, const int* __restrict__ col, int e) {
    int i = blockIdx.x * blockDim.x + threadIdx.x;
    if (i < e) {
        int r = row[i];
        int pos = g_rowptr[r] + atomicAdd(&g_fill[r], 1);
        g_csrcol[pos] = col[i];
    }
}

// ---------------- W1 transpose -> bf16 [n][k] ----------------
__global__ void k_w1t(const float* __restrict__ W1) {
    __shared__ float tile[32][33];
    int bx = blockIdx.x * 32, by = blockIdx.y * 32;
    int tx = threadIdx.x, ty = threadIdx.y;
#pragma unroll
    for (int i = 0; i < 4; i++)
        tile[ty + i * 8][tx] = W1[(size_t)(by + ty + i * 8) * FD + bx + tx];
    __syncthreads();
#pragma unroll
    for (int i = 0; i < 4; i++)
        g_w1t[(size_t)(bx + ty + i * 8) * FD + by + tx] =
            __float2bfloat16(tile[tx][ty + i * 8]);
}

// ---------------- bf16 HMMA helpers ----------------
__device__ __forceinline__ void mma_bf16(float* d, const uint32_t* a, const uint32_t* b) {
    asm volatile(
        "mma.sync.aligned.m16n8k16.row.col.f32.bf16.bf16.f32 "
        "{%0,%1,%2,%3}, {%4,%5,%6,%7}, {%8,%9}, {%0,%1,%2,%3};\n"
        : "+f"(d[0]), "+f"(d[1]), "+f"(d[2]), "+f"(d[3])
        : "r"(a[0]), "r"(a[1]), "r"(a[2]), "r"(a[3]), "r"(b[0]), "r"(b[1]));
}

#define BM 128
#define BN 128
#define BK 32
#define ASTR 40   // bf16 row stride (32 data + 8 pad) -> conflict-free fragment loads

// ---------------- GEMM1: tb = bf16(relu(x @ W1 + b1)) ----------------
__global__ __launch_bounds__(256, 2) void k_gemm1(const float* __restrict__ A,
                                                  const float* __restrict__ bias, int n) {
    __shared__ __nv_bfloat16 As[BM * ASTR];
    __shared__ __nv_bfloat16 Bs[BN * ASTR];
    int tid = threadIdx.x;
    int lane = tid & 31, warp = tid >> 5;
    int wm = (warp & 3) * 32;
    int wn = (warp >> 2) * 64;
    int r0 = blockIdx.x * BM, c0 = blockIdx.y * BN;

    float acc[2][8][4];
#pragma unroll
    for (int mi = 0; mi < 2; mi++)
#pragma unroll
        for (int ni = 0; ni < 8; ni++)
#pragma unroll
            for (int j = 0; j < 4; j++) acc[mi][ni][j] = 0.f;

    for (int k0 = 0; k0 < FD; k0 += BK) {
#pragma unroll
        for (int it = 0; it < 4; it++) {
            int idx = tid + it * 256;
            int row = idx >> 3;
            int q   = idx & 7;
            int gr  = r0 + row;
            float4 v = (gr < n) ? *(const float4*)(A + (size_t)gr * FD + k0 + q * 4)
                                : make_float4(0.f, 0.f, 0.f, 0.f);
            __nv_bfloat162 p0 = __floats2bfloat162_rn(v.x, v.y);
            __nv_bfloat162 p1 = __floats2bfloat162_rn(v.z, v.w);
            *(uint2*)(As + row * ASTR + q * 4) = make_uint2(*(uint32_t*)&p0, *(uint32_t*)&p1);
        }
#pragma unroll
        for (int it = 0; it < 2; it++) {
            int idx = tid + it * 256;
            int row = idx >> 2;
            int q   = idx & 3;
            uint4 v = *(const uint4*)(g_w1t + (size_t)(c0 + row) * FD + k0 + q * 8);
            *(uint4*)(Bs + row * ASTR + q * 8) = v;
        }
        __syncthreads();

        int g = lane >> 2, q = lane & 3;
#pragma unroll
        for (int ks = 0; ks < 2; ks++) {
            uint32_t afr[2][4], bfr[8][2];
#pragma unroll
            for (int mi = 0; mi < 2; mi++) {
                const __nv_bfloat16* base = As + (wm + mi * 16 + g) * ASTR + ks * 16 + q * 2;
                afr[mi][0] = *(const uint32_t*)(base);
                afr[mi][1] = *(const uint32_t*)(base + 8 * ASTR);
                afr[mi][2] = *(const uint32_t*)(base + 8);
                afr[mi][3] = *(const uint32_t*)(base + 8 * ASTR + 8);
            }
#pragma unroll
            for (int ni = 0; ni < 8; ni++) {
                const __nv_bfloat16* base = Bs + (wn + ni * 8 + g) * ASTR + ks * 16 + q * 2;
                bfr[ni][0] = *(const uint32_t*)(base);
                bfr[ni][1] = *(const uint32_t*)(base + 8);
            }
#pragma unroll
            for (int mi = 0; mi < 2; mi++)
#pragma unroll
                for (int ni = 0; ni < 8; ni++)
                    mma_bf16(acc[mi][ni], afr[mi], bfr[ni]);
        }
        __syncthreads();
    }

    // epilogue: bias + relu -> g_tb (bf16)
    int g = lane >> 2, q = lane & 3;
#pragma unroll
    for (int mi = 0; mi < 2; mi++) {
        int row = r0 + wm + mi * 16 + g;
#pragma unroll
        for (int ni = 0; ni < 8; ni++) {
            int col = c0 + wn + ni * 8 + q * 2;
            float bb0 = bias[col], bb1 = bias[col + 1];
            if (row < n) {
                *(__nv_bfloat162*)(g_tb + (size_t)row * FD + col) =
                    __floats2bfloat162_rn(fmaxf(acc[mi][ni][0] + bb0, 0.f),
                                          fmaxf(acc[mi][ni][1] + bb1, 0.f));
            }
            if (row + 8 < n) {
                *(__nv_bfloat162*)(g_tb + (size_t)(row + 8) * FD + col) =
                    __floats2bfloat162_rn(fmaxf(acc[mi][ni][2] + bb0, 0.f),
                                          fmaxf(acc[mi][ni][3] + bb1, 0.f));
            }
        }
    }
}

// ---------------- build Wr^T bf16 [120][512]: rows = [Wa|Wb|Wc] cols ----------------
__global__ void k_buildwr(const float* __restrict__ W2) {
    int idx = blockIdx.x * blockDim.x + threadIdx.x;   // c*512 + k
    if (idx >= NCOL * FD) return;
    int c = idx / FD, k = idx % FD;
    float v;
    if (c < 40)       v = W2[k * NC + c]               + W2[(k + 512) * NC + c];
    else if (c < 80)  v = W2[(k + 1024) * NC + c - 40] + W2[(k + 1536) * NC + c - 40];
    else              v = W2[(k + 2048) * NC + c - 80];
    g_wrb[idx] = __float2bfloat16(v);
}

// ---------------- bf16 GEMM2a: P = t @ Wr  [n,512]x[512,120] ----------------
// 128 rows/block, 256 thr (8 warps, warp w owns rows w*16..+15)
__global__ __launch_bounds__(256) void k_gemm2a(int n) {
    __shared__ __nv_bfloat16 As[BM * ASTR];
    __shared__ __nv_bfloat16 Ws[NCOL * ASTR];

    int tid  = threadIdx.x;
    int lane = tid & 31, warp = tid >> 5;
    int r0   = blockIdx.x * 128;

    float acc[15][4];
#pragma unroll
    for (int t = 0; t < 15; t++)
#pragma unroll
        for (int j = 0; j < 4; j++) acc[t][j] = 0.f;

    for (int k0 = 0; k0 < FD; k0 += BK) {
        // A tile: 128 rows x 32 bf16 from g_tb
#pragma unroll
        for (int it = 0; it < 2; it++) {
            int idx = tid + it * 256;      // 0..511
            int row = idx >> 2;
            int q   = idx & 3;
            int gr  = r0 + row;
            uint4 v = (gr < n) ? *(const uint4*)(g_tb + (size_t)gr * FD + k0 + q * 8)
                               : make_uint4(0, 0, 0, 0);
            *(uint4*)(As + row * ASTR + q * 8) = v;
        }
        // B tile: 120 n-rows x 32 bf16 from g_wrb
        {
            int idx = tid;                 // 480 uint4 needed
            if (idx < 480) {
                int row = idx >> 2, q = idx & 3;
                uint4 v = *(const uint4*)(g_wrb + (size_t)row * FD + k0 + q * 8);
                *(uint4*)(Ws + row * ASTR + q * 8) = v;
            }
            idx = tid + 256;
            if (idx < 480) {
                int row = idx >> 2, q = idx & 3;
                uint4 v = *(const uint4*)(g_wrb + (size_t)row * FD + k0 + q * 8);
                *(uint4*)(Ws + row * ASTR + q * 8) = v;
            }
        }
        __syncthreads();

        int g = lane >> 2, q = lane & 3;
#pragma unroll
        for (int ks = 0; ks < 2; ks++) {
            uint32_t a[4];
            const __nv_bfloat16* abase = As + (warp * 16 + g) * ASTR + ks * 16 + q * 2;
            a[0] = *(const uint32_t*)(abase);
            a[1] = *(const uint32_t*)(abase + 8 * ASTR);
            a[2] = *(const uint32_t*)(abase + 8);
            a[3] = *(const uint32_t*)(abase + 8 * ASTR + 8);
#pragma unroll
            for (int t = 0; t < 15; t++) {
                uint32_t b[2];
                const __nv_bfloat16* bbase = Ws + (t * 8 + g) * ASTR + ks * 16 + q * 2;
                b[0] = *(const uint32_t*)(bbase);
                b[1] = *(const uint32_t*)(bbase + 8);
                mma_bf16(acc[t], a, b);
            }
        }
        __syncthreads();
    }

    // epilogue: cols 0..39 -> g_p0 (stride 40), 40..119 -> g_p12 (stride 80)
    int g = lane >> 2, q = lane & 3;
    int rlo = r0 + warp * 16 + g;
    int rhi = rlo + 8;
#pragma unroll
    for (int t = 0; t < 15; t++) {
        int c = t * 8 + q * 2;
        if (rlo < n) {
            float2 v = make_float2(acc[t][0], acc[t][1]);
            if (c < 40) *(float2*)(g_p0  + (size_t)rlo * 40 + c)      = v;
            else        *(float2*)(g_p12 + (size_t)rlo * 80 + c - 40) = v;
        }
        if (rhi < n) {
            float2 v = make_float2(acc[t][2], acc[t][3]);
            if (c < 40) *(float2*)(g_p0  + (size_t)rhi * 40 + c)      = v;
            else        *(float2*)(g_p12 + (size_t)rhi * 80 + c - 40) = v;
        }
    }
}

// ---------------- SpMM-A: Q12 = Ahat @ P12  (80-wide, warp per node) ----------------
__global__ __launch_bounds__(256) void k_spmmA(int n) {
    int node = blockIdx.x * 8 + (threadIdx.x >> 5);
    int lane = threadIdx.x & 31;
    if (node >= n) return;

    float di = g_dinv[node];
    const float4* P = (const float4*)g_p12;
    float4 acc = make_float4(0, 0, 0, 0);
    if (lane < 20) {
        float4 s = P[(size_t)node * 20 + lane];
        float w = di * di;
        acc.x = s.x * w; acc.y = s.y * w; acc.z = s.z * w; acc.w = s.w * w;
    }

    int beg = g_rowptr[node], end = g_rowptr[node + 1];
    for (int b = beg; b < end; b += 32) {
        int m = end - b; if (m > 32) m = 32;
        int c = 0; float w = 0.f;
        if (lane < m) { c = g_csrcol[b + lane]; w = di * g_dinv[c]; }
        int jj = 0;
        for (; jj + 4 <= m; jj += 4) {
            int   c0 = __shfl_sync(0xffffffffu, c, jj);
            int   c1 = __shfl_sync(0xffffffffu, c, jj + 1);
            int   c2 = __shfl_sync(0xffffffffu, c, jj + 2);
            int   c3 = __shfl_sync(0xffffffffu, c, jj + 3);
            float w0 = __shfl_sync(0xffffffffu, w, jj);
            float w1 = __shfl_sync(0xffffffffu, w, jj + 1);
            float w2 = __shfl_sync(0xffffffffu, w, jj + 2);
            float w3 = __shfl_sync(0xffffffffu, w, jj + 3);
            if (lane < 20) {
                float4 v0 = P[(size_t)c0 * 20 + lane];
                float4 v1 = P[(size_t)c1 * 20 + lane];
                float4 v2 = P[(size_t)c2 * 20 + lane];
                float4 v3 = P[(size_t)c3 * 20 + lane];
                acc.x += w0 * v0.x; acc.y += w0 * v0.y; acc.z += w0 * v0.z; acc.w += w0 * v0.w;
                acc.x += w1 * v1.x; acc.y += w1 * v1.y; acc.z += w1 * v1.z; acc.w += w1 * v1.w;
                acc.x += w2 * v2.x; acc.y += w2 * v2.y; acc.z += w2 * v2.z; acc.w += w2 * v2.w;
                acc.x += w3 * v3.x; acc.y += w3 * v3.y; acc.z += w3 * v3.z; acc.w += w3 * v3.w;
            }
        }
        for (; jj < m; jj++) {
            int   cc = __shfl_sync(0xffffffffu, c, jj);
            float ww = __shfl_sync(0xffffffffu, w, jj);
            if (lane < 20) {
                float4 v = P[(size_t)cc * 20 + lane];
                acc.x += ww * v.x; acc.y += ww * v.y; acc.z += ww * v.z; acc.w += ww * v.w;
            }
        }
    }
    if (lane < 20) ((float4*)g_q12)[(size_t)node * 20 + lane] = acc;
}

// ---------------- SpMM-B: R = Ahat @ Q2  (40-wide) ----------------
__global__ __launch_bounds__(256) void k_spmmB(int n) {
    int node = blockIdx.x * 8 + (threadIdx.x >> 5);
    int lane = threadIdx.x & 31;
    if (node >= n) return;

    float di = g_dinv[node];
    const float4* Q = (const float4*)g_q12;
    float4 acc = make_float4(0, 0, 0, 0);
    if (lane < 10) {
        float4 s = Q[(size_t)node * 20 + 10 + lane];
        float w = di * di;
        acc.x = s.x * w; acc.y = s.y * w; acc.z = s.z * w; acc.w = s.w * w;
    }

    int beg = g_rowptr[node], end = g_rowptr[node + 1];
    for (int b = beg; b < end; b += 32) {
        int m = end - b; if (m > 32) m = 32;
        int c = 0; float w = 0.f;
        if (lane < m) { c = g_csrcol[b + lane]; w = di * g_dinv[c]; }
        int jj = 0;
        for (; jj + 4 <= m; jj += 4) {
            int   c0 = __shfl_sync(0xffffffffu, c, jj);
            int   c1 = __shfl_sync(0xffffffffu, c, jj + 1);
            int   c2 = __shfl_sync(0xffffffffu, c, jj + 2);
            int   c3 = __shfl_sync(0xffffffffu, c, jj + 3);
            float w0 = __shfl_sync(0xffffffffu, w, jj);
            float w1 = __shfl_sync(0xffffffffu, w, jj + 1);
            float w2 = __shfl_sync(0xffffffffu, w, jj + 2);
            float w3 = __shfl_sync(0xffffffffu, w, jj + 3);
            if (lane < 10) {
                float4 v0 = Q[(size_t)c0 * 20 + 10 + lane];
                float4 v1 = Q[(size_t)c1 * 20 + 10 + lane];
                float4 v2 = Q[(size_t)c2 * 20 + 10 + lane];
                float4 v3 = Q[(size_t)c3 * 20 + 10 + lane];
                acc.x += w0 * v0.x; acc.y += w0 * v0.y; acc.z += w0 * v0.z; acc.w += w0 * v0.w;
                acc.x += w1 * v1.x; acc.y += w1 * v1.y; acc.z += w1 * v1.z; acc.w += w1 * v1.w;
                acc.x += w2 * v2.x; acc.y += w2 * v2.y; acc.z += w2 * v2.z; acc.w += w2 * v2.w;
                acc.x += w3 * v3.x; acc.y += w3 * v3.y; acc.z += w3 * v3.z; acc.w += w3 * v3.w;
            }
        }
        for (; jj < m; jj++) {
            int   cc = __shfl_sync(0xffffffffu, c, jj);
            float ww = __shfl_sync(0xffffffffu, w, jj);
            if (lane < 10) {
                float4 v = Q[(size_t)cc * 20 + 10 + lane];
                acc.x += ww * v.x; acc.y += ww * v.y; acc.z += ww * v.z; acc.w += ww * v.w;
            }
        }
    }
    if (lane < 10) ((float4*)g_r)[(size_t)node * 10 + lane] = acc;
}

// ---------------- final: out = log_softmax(P0 + Q1 + R + b2) ----------------
__global__ __launch_bounds__(256) void k_final(const float* __restrict__ b2,
                                               float* __restrict__ out, int n) {
    int node = blockIdx.x * 8 + (threadIdx.x >> 5);
    int lane = threadIdx.x & 31;
    if (node >= n) return;

    float2 v = make_float2(0.f, 0.f);
    if (lane < 20) {
        float2 a = ((const float2*)g_p0) [(size_t)node * 20 + lane];
        float2 b = ((const float2*)g_q12)[(size_t)node * 40 + lane];
        float2 r = ((const float2*)g_r)  [(size_t)node * 20 + lane];
        float2 bb = ((const float2*)b2)[lane];
        v.x = a.x + b.x + r.x + bb.x;
        v.y = a.y + b.y + r.y + bb.y;
    }

    float m = (lane < 20) ? fmaxf(v.x, v.y) : -1e30f;
#pragma unroll
    for (int o = 16; o > 0; o >>= 1) m = fmaxf(m, __shfl_xor_sync(0xffffffffu, m, o));
    float s = (lane < 20) ? (expf(v.x - m) + expf(v.y - m)) : 0.f;
#pragma unroll
    for (int o = 16; o > 0; o >>= 1) s += __shfl_xor_sync(0xffffffffu, s, o);
    float z = m + logf(s);

    if (lane < 20) {
        float2 o2 = make_float2(v.x - z, v.y - z);
        *(float2*)(out + (size_t)node * NC + lane * 2) = o2;
    }
}

// ---------------- launch ----------------
extern "C" void kernel_launch(void* const* d_in, const int* in_sizes, int n_in,
                              void* d_out, int out_size) {
    const float* x    = (const float*)d_in[0];
    const int*   erow = (const int*)  d_in[1];
    const int*   ecol = (const int*)  d_in[2];
    const float* W1   = (const float*)d_in[3];
    const float* b1   = (const float*)d_in[4];
    const float* W2   = (const float*)d_in[5];
    const float* b2   = (const float*)d_in[6];
    float* out = (float*)d_out;

    int n = in_sizes[0] / FD;   // 50000
    int e = in_sizes[1];        // 1600000
    (void)n_in; (void)out_size;

    int nb  = (n + 1023) / 1024;
    int nwb = (n + 7) / 8;

    // 1) degree / dinv / CSR build
    k_init   <<<(n + 255) / 256, 256>>>(n);
    k_count  <<<(e + 255) / 256, 256>>>(erow, ecol, e);
    k_scan1  <<<nb, 256>>>(n);           // also computes dinv
    k_scan2  <<<1, 1>>>(nb, n);
    k_scan3  <<<nb, 256>>>(n);
    k_scatter<<<(e + 255) / 256, 256>>>(erow, ecol, e);

    // 2) tb = bf16(relu(x @ W1 + b1))  [bf16 HMMA]
    k_w1t<<<dim3(16, 16), dim3(32, 8)>>>(W1);
    dim3 g1((n + 127) / 128, FD / 128);
    k_gemm1<<<g1, 256>>>(x, b1, n);

    // 3) P = tb @ [Wa|Wb|Wc]  [bf16 HMMA]
    k_buildwr<<<(NCOL * FD + 255) / 256, 256>>>(W2);
    k_gemm2a<<<(n + 127) / 128, 256>>>(n);

    // 4) Q12 = Ahat P12 ; R = Ahat Q2
    k_spmmA<<<nwb, 256>>>(n);
    k_spmmB<<<nwb, 256>>>(n);

    // 5) out = log_softmax(P0 + Q1 + R + b2)
    k_final<<<nwb, 256>>>(b2, out, n);
}

// round 13
// speedup vs baseline: 4.0836x; 1.0369x over previous
#include <cuda_runtime.h>
#include <cuda_bf16.h>
#include <math.h>
#include <stdint.h>

#define NN 50000
#define EE 1600000
#define FD 512
#define NC 40
#define NCOL 120   // [Wa|Wb|Wc] columns

// ---------------- device scratch ----------------
__device__ float g_deg[NN];
__device__ float g_dinv[NN];
__device__ __align__(16) int g_cnt[NN];
__device__ int   g_fill[NN];
__device__ int   g_rowptr[NN + 1];
__device__ int   g_csrcol[EE];
__device__ int   g_bsum[64];
__device__ __align__(16) __nv_bfloat16 g_tb[(size_t)NN * FD];  // relu(xW1+b1), bf16
__device__ __align__(16) float g_p0 [(size_t)NN * 40];   // t*Wa
__device__ __align__(16) float g_p12[(size_t)NN * 80];   // [t*Wb | t*Wc]
__device__ __align__(16) float g_q12[(size_t)NN * 80];   // [A p1 | A p2]
__device__ __align__(16) __nv_bfloat16 g_wrb[NCOL * FD]; // [Wa|Wb|Wc]^T bf16 [n][k]
__device__ __align__(16) __nv_bfloat16 g_w1t[FD * FD];   // W1 transposed, bf16 [n][k]

// ---------------- preprocessing ----------------
__global__ void k_init(int n) {
    int i = blockIdx.x * blockDim.x + threadIdx.x;
    if (i < n) { g_deg[i] = 1.0f; g_cnt[i] = 0; g_fill[i] = 0; }
}

__global__ void k_count(const int* __restrict__ row, const int* __restrict__ col, int e) {
    int i = blockIdx.x * blockDim.x + threadIdx.x;
    if (i < e) {
        atomicAdd(&g_deg[col[i]], 1.0f);
        atomicAdd(&g_cnt[row[i]], 1);
    }
}

// scan phase 1 + dinv fused
__global__ void k_scan1(int n) {
    __shared__ int sh[256];
    int b = blockIdx.x, t = threadIdx.x;
    int i = b * 1024 + t * 4;
    for (int j = 0; j < 4; j++)
        if (i + j < n) g_dinv[i + j] = rsqrtf(g_deg[i + j]);
    int s = 0;
    if (i + 3 < n) { int4 v = *(const int4*)(g_cnt + i); s = v.x + v.y + v.z + v.w; }
    else { for (int j = 0; j < 4; j++) if (i + j < n) s += g_cnt[i + j]; }
    sh[t] = s; __syncthreads();
    for (int o = 128; o > 0; o >>= 1) { if (t < o) sh[t] += sh[t + o]; __syncthreads(); }
    if (t == 0) g_bsum[b] = sh[0];
}

// scan phase 2+3 fused: inline prefix of g_bsum (tiny) + intra-block exclusive scan
__global__ void k_scan3(int nb, int n) {
    __shared__ int sh[256];
    int b = blockIdx.x, t = threadIdx.x;
    int i = b * 1024 + t * 4;
    int c0 = 0, c1 = 0, c2 = 0, c3 = 0;
    if (i + 3 < n) { int4 v = *(const int4*)(g_cnt + i); c0 = v.x; c1 = v.y; c2 = v.z; c3 = v.w; }
    else {
        if (i     < n) c0 = g_cnt[i];
        if (i + 1 < n) c1 = g_cnt[i + 1];
        if (i + 2 < n) c2 = g_cnt[i + 2];
        if (i + 3 < n) c3 = g_cnt[i + 3];
    }
    int s = c0 + c1 + c2 + c3;
    sh[t] = s; __syncthreads();
    for (int o = 1; o < 256; o <<= 1) {
        int v = (t >= o) ? sh[t - o] : 0;
        __syncthreads();
        sh[t] += v;
        __syncthreads();
    }
    // block prefix over g_bsum[0..b)
    int bpre = 0;
    for (int bb = 0; bb < b; bb++) bpre += g_bsum[bb];
    if (b == 0 && t == 0) {
        int tot = 0;
        for (int bb = 0; bb < nb; bb++) tot += g_bsum[bb];
        g_rowptr[n] = tot;
    }
    int base = bpre + ((t > 0) ? sh[t - 1] : 0);
    if (i     < n) { g_rowptr[i]     = base; base += c0; }
    if (i + 1 < n) { g_rowptr[i + 1] = base; base += c1; }
    if (i + 2 < n) { g_rowptr[i + 2] = base; base += c2; }
    if (i + 3 < n) { g_rowptr[i + 3] = base; }
}

__global__ void k_scatter(const int* __restrict__ row, const int* __restrict__ col, int e) {
    int i = blockIdx.x * blockDim.x + threadIdx.x;
    if (i < e) {
        int r = row[i];
        int pos = g_rowptr[r] + atomicAdd(&g_fill[r], 1);
        g_csrcol[pos] = col[i];
    }
}

// ---------------- W1 transpose -> bf16 [n][k] ----------------
__global__ void k_w1t(const float* __restrict__ W1) {
    __shared__ float tile[32][33];
    int bx = blockIdx.x * 32, by = blockIdx.y * 32;
    int tx = threadIdx.x, ty = threadIdx.y;
#pragma unroll
    for (int i = 0; i < 4; i++)
        tile[ty + i * 8][tx] = W1[(size_t)(by + ty + i * 8) * FD + bx + tx];
    __syncthreads();
#pragma unroll
    for (int i = 0; i < 4; i++)
        g_w1t[(size_t)(bx + ty + i * 8) * FD + by + tx] =
            __float2bfloat16(tile[tx][ty + i * 8]);
}

// ---------------- bf16 HMMA helpers ----------------
__device__ __forceinline__ void mma_bf16(float* d, const uint32_t* a, const uint32_t* b) {
    asm volatile(
        "mma.sync.aligned.m16n8k16.row.col.f32.bf16.bf16.f32 "
        "{%0,%1,%2,%3}, {%4,%5,%6,%7}, {%8,%9}, {%0,%1,%2,%3};\n"
        : "+f"(d[0]), "+f"(d[1]), "+f"(d[2]), "+f"(d[3])
        : "r"(a[0]), "r"(a[1]), "r"(a[2]), "r"(a[3]), "r"(b[0]), "r"(b[1]));
}

#define BM 128
#define BN 128
#define BK 32
#define ASTR 40   // bf16 row stride (32 data + 8 pad) -> conflict-free fragment loads

// ---------------- GEMM1: tb = bf16(relu(x @ W1 + b1)) ----------------
// grid (4 col-tiles, 391 row-tiles): col index fastest -> x row-tile reused from L2
__global__ __launch_bounds__(256, 2) void k_gemm1(const float* __restrict__ A,
                                                  const float* __restrict__ bias, int n) {
    __shared__ __nv_bfloat16 As[BM * ASTR];
    __shared__ __nv_bfloat16 Bs[BN * ASTR];
    int tid = threadIdx.x;
    int lane = tid & 31, warp = tid >> 5;
    int wm = (warp & 3) * 32;
    int wn = (warp >> 2) * 64;
    int r0 = blockIdx.y * BM, c0 = blockIdx.x * BN;

    float acc[2][8][4];
#pragma unroll
    for (int mi = 0; mi < 2; mi++)
#pragma unroll
        for (int ni = 0; ni < 8; ni++)
#pragma unroll
            for (int j = 0; j < 4; j++) acc[mi][ni][j] = 0.f;

    for (int k0 = 0; k0 < FD; k0 += BK) {
#pragma unroll
        for (int it = 0; it < 4; it++) {
            int idx = tid + it * 256;
            int row = idx >> 3;
            int q   = idx & 7;
            int gr  = r0 + row;
            float4 v = (gr < n) ? *(const float4*)(A + (size_t)gr * FD + k0 + q * 4)
                                : make_float4(0.f, 0.f, 0.f, 0.f);
            __nv_bfloat162 p0 = __floats2bfloat162_rn(v.x, v.y);
            __nv_bfloat162 p1 = __floats2bfloat162_rn(v.z, v.w);
            *(uint2*)(As + row * ASTR + q * 4) = make_uint2(*(uint32_t*)&p0, *(uint32_t*)&p1);
        }
#pragma unroll
        for (int it = 0; it < 2; it++) {
            int idx = tid + it * 256;
            int row = idx >> 2;
            int q   = idx & 3;
            uint4 v = *(const uint4*)(g_w1t + (size_t)(c0 + row) * FD + k0 + q * 8);
            *(uint4*)(Bs + row * ASTR + q * 8) = v;
        }
        __syncthreads();

        int g = lane >> 2, q = lane & 3;
#pragma unroll
        for (int ks = 0; ks < 2; ks++) {
            uint32_t afr[2][4], bfr[8][2];
#pragma unroll
            for (int mi = 0; mi < 2; mi++) {
                const __nv_bfloat16* base = As + (wm + mi * 16 + g) * ASTR + ks * 16 + q * 2;
                afr[mi][0] = *(const uint32_t*)(base);
                afr[mi][1] = *(const uint32_t*)(base + 8 * ASTR);
                afr[mi][2] = *(const uint32_t*)(base + 8);
                afr[mi][3] = *(const uint32_t*)(base + 8 * ASTR + 8);
            }
#pragma unroll
            for (int ni = 0; ni < 8; ni++) {
                const __nv_bfloat16* base = Bs + (wn + ni * 8 + g) * ASTR + ks * 16 + q * 2;
                bfr[ni][0] = *(const uint32_t*)(base);
                bfr[ni][1] = *(const uint32_t*)(base + 8);
            }
#pragma unroll
            for (int mi = 0; mi < 2; mi++)
#pragma unroll
                for (int ni = 0; ni < 8; ni++)
                    mma_bf16(acc[mi][ni], afr[mi], bfr[ni]);
        }
        __syncthreads();
    }

    // epilogue: bias + relu -> g_tb (bf16)
    int g = lane >> 2, q = lane & 3;
#pragma unroll
    for (int mi = 0; mi < 2; mi++) {
        int row = r0 + wm + mi * 16 + g;
#pragma unroll
        for (int ni = 0; ni < 8; ni++) {
            int col = c0 + wn + ni * 8 + q * 2;
            float bb0 = bias[col], bb1 = bias[col + 1];
            if (row < n) {
                *(__nv_bfloat162*)(g_tb + (size_t)row * FD + col) =
                    __floats2bfloat162_rn(fmaxf(acc[mi][ni][0] + bb0, 0.f),
                                          fmaxf(acc[mi][ni][1] + bb1, 0.f));
            }
            if (row + 8 < n) {
                *(__nv_bfloat162*)(g_tb + (size_t)(row + 8) * FD + col) =
                    __floats2bfloat162_rn(fmaxf(acc[mi][ni][2] + bb0, 0.f),
                                          fmaxf(acc[mi][ni][3] + bb1, 0.f));
            }
        }
    }
}

// ---------------- build Wr^T bf16 [120][512] ----------------
__global__ void k_buildwr(const float* __restrict__ W2) {
    int idx = blockIdx.x * blockDim.x + threadIdx.x;   // c*512 + k
    if (idx >= NCOL * FD) return;
    int c = idx / FD, k = idx % FD;
    float v;
    if (c < 40)       v = W2[k * NC + c]               + W2[(k + 512) * NC + c];
    else if (c < 80)  v = W2[(k + 1024) * NC + c - 40] + W2[(k + 1536) * NC + c - 40];
    else              v = W2[(k + 2048) * NC + c - 80];
    g_wrb[idx] = __float2bfloat16(v);
}

// ---------------- bf16 GEMM2a: P = t @ Wr  [n,512]x[512,120] ----------------
__global__ __launch_bounds__(256) void k_gemm2a(int n) {
    __shared__ __nv_bfloat16 As[BM * ASTR];
    __shared__ __nv_bfloat16 Ws[NCOL * ASTR];

    int tid  = threadIdx.x;
    int lane = tid & 31, warp = tid >> 5;
    int r0   = blockIdx.x * 128;

    float acc[15][4];
#pragma unroll
    for (int t = 0; t < 15; t++)
#pragma unroll
        for (int j = 0; j < 4; j++) acc[t][j] = 0.f;

    for (int k0 = 0; k0 < FD; k0 += BK) {
#pragma unroll
        for (int it = 0; it < 2; it++) {
            int idx = tid + it * 256;
            int row = idx >> 2;
            int q   = idx & 3;
            int gr  = r0 + row;
            uint4 v = (gr < n) ? *(const uint4*)(g_tb + (size_t)gr * FD + k0 + q * 8)
                               : make_uint4(0, 0, 0, 0);
            *(uint4*)(As + row * ASTR + q * 8) = v;
        }
        {
            int idx = tid;
            if (idx < 480) {
                int row = idx >> 2, q = idx & 3;
                uint4 v = *(const uint4*)(g_wrb + (size_t)row * FD + k0 + q * 8);
                *(uint4*)(Ws + row * ASTR + q * 8) = v;
            }
            idx = tid + 256;
            if (idx < 480) {
                int row = idx >> 2, q = idx & 3;
                uint4 v = *(const uint4*)(g_wrb + (size_t)row * FD + k0 + q * 8);
                *(uint4*)(Ws + row * ASTR + q * 8) = v;
            }
        }
        __syncthreads();

        int g = lane >> 2, q = lane & 3;
#pragma unroll
        for (int ks = 0; ks < 2; ks++) {
            uint32_t a[4];
            const __nv_bfloat16* abase = As + (warp * 16 + g) * ASTR + ks * 16 + q * 2;
            a[0] = *(const uint32_t*)(abase);
            a[1] = *(const uint32_t*)(abase + 8 * ASTR);
            a[2] = *(const uint32_t*)(abase + 8);
            a[3] = *(const uint32_t*)(abase + 8 * ASTR + 8);
#pragma unroll
            for (int t = 0; t < 15; t++) {
                uint32_t b[2];
                const __nv_bfloat16* bbase = Ws + (t * 8 + g) * ASTR + ks * 16 + q * 2;
                b[0] = *(const uint32_t*)(bbase);
                b[1] = *(const uint32_t*)(bbase + 8);
                mma_bf16(acc[t], a, b);
            }
        }
        __syncthreads();
    }

    int g = lane >> 2, q = lane & 3;
    int rlo = r0 + warp * 16 + g;
    int rhi = rlo + 8;
#pragma unroll
    for (int t = 0; t < 15; t++) {
        int c = t * 8 + q * 2;
        if (rlo < n) {
            float2 v = make_float2(acc[t][0], acc[t][1]);
            if (c < 40) *(float2*)(g_p0  + (size_t)rlo * 40 + c)      = v;
            else        *(float2*)(g_p12 + (size_t)rlo * 80 + c - 40) = v;
        }
        if (rhi < n) {
            float2 v = make_float2(acc[t][2], acc[t][3]);
            if (c < 40) *(float2*)(g_p0  + (size_t)rhi * 40 + c)      = v;
            else        *(float2*)(g_p12 + (size_t)rhi * 80 + c - 40) = v;
        }
    }
}

// ---------------- SpMM-A: Q12 = Ahat @ P12  (80-wide, warp per node) ----------------
__global__ __launch_bounds__(256) void k_spmmA(int n) {
    int node = blockIdx.x * 8 + (threadIdx.x >> 5);
    int lane = threadIdx.x & 31;
    if (node >= n) return;

    float di = g_dinv[node];
    const float4* P = (const float4*)g_p12;
    float4 acc = make_float4(0, 0, 0, 0);
    if (lane < 20) {
        float4 s = P[(size_t)node * 20 + lane];
        float w = di * di;
        acc.x = s.x * w; acc.y = s.y * w; acc.z = s.z * w; acc.w = s.w * w;
    }

    int beg = g_rowptr[node], end = g_rowptr[node + 1];
    for (int b = beg; b < end; b += 32) {
        int m = end - b; if (m > 32) m = 32;
        int c = 0; float w = 0.f;
        if (lane < m) { c = g_csrcol[b + lane]; w = di * g_dinv[c]; }
        int jj = 0;
        for (; jj + 4 <= m; jj += 4) {
            int   c0 = __shfl_sync(0xffffffffu, c, jj);
            int   c1 = __shfl_sync(0xffffffffu, c, jj + 1);
            int   c2 = __shfl_sync(0xffffffffu, c, jj + 2);
            int   c3 = __shfl_sync(0xffffffffu, c, jj + 3);
            float w0 = __shfl_sync(0xffffffffu, w, jj);
            float w1 = __shfl_sync(0xffffffffu, w, jj + 1);
            float w2 = __shfl_sync(0xffffffffu, w, jj + 2);
            float w3 = __shfl_sync(0xffffffffu, w, jj + 3);
            if (lane < 20) {
                float4 v0 = P[(size_t)c0 * 20 + lane];
                float4 v1 = P[(size_t)c1 * 20 + lane];
                float4 v2 = P[(size_t)c2 * 20 + lane];
                float4 v3 = P[(size_t)c3 * 20 + lane];
                acc.x += w0 * v0.x; acc.y += w0 * v0.y; acc.z += w0 * v0.z; acc.w += w0 * v0.w;
                acc.x += w1 * v1.x; acc.y += w1 * v1.y; acc.z += w1 * v1.z; acc.w += w1 * v1.w;
                acc.x += w2 * v2.x; acc.y += w2 * v2.y; acc.z += w2 * v2.z; acc.w += w2 * v2.w;
                acc.x += w3 * v3.x; acc.y += w3 * v3.y; acc.z += w3 * v3.z; acc.w += w3 * v3.w;
            }
        }
        for (; jj < m; jj++) {
            int   cc = __shfl_sync(0xffffffffu, c, jj);
            float ww = __shfl_sync(0xffffffffu, w, jj);
            if (lane < 20) {
                float4 v = P[(size_t)cc * 20 + lane];
                acc.x += ww * v.x; acc.y += ww * v.y; acc.z += ww * v.z; acc.w += ww * v.w;
            }
        }
    }
    if (lane < 20) ((float4*)g_q12)[(size_t)node * 20 + lane] = acc;
}

// ---------------- SpMM-B fused with final log_softmax ----------------
// r = Ahat @ Q2 (40-wide); out = log_softmax(P0 + Q1 + r + b2)
__global__ __launch_bounds__(256) void k_spmmB_final(const float* __restrict__ b2,
                                                     float* __restrict__ out, int n) {
    int node = blockIdx.x * 8 + (threadIdx.x >> 5);
    int lane = threadIdx.x & 31;
    if (node >= n) return;

    float di = g_dinv[node];
    const float4* Q = (const float4*)g_q12;
    float4 acc = make_float4(0, 0, 0, 0);
    if (lane < 10) {
        float4 s = Q[(size_t)node * 20 + 10 + lane];
        float w = di * di;
        acc.x = s.x * w; acc.y = s.y * w; acc.z = s.z * w; acc.w = s.w * w;
    }

    int beg = g_rowptr[node], end = g_rowptr[node + 1];
    for (int b = beg; b < end; b += 32) {
        int m = end - b; if (m > 32) m = 32;
        int c = 0; float w = 0.f;
        if (lane < m) { c = g_csrcol[b + lane]; w = di * g_dinv[c]; }
        int jj = 0;
        for (; jj + 4 <= m; jj += 4) {
            int   c0 = __shfl_sync(0xffffffffu, c, jj);
            int   c1 = __shfl_sync(0xffffffffu, c, jj + 1);
            int   c2 = __shfl_sync(0xffffffffu, c, jj + 2);
            int   c3 = __shfl_sync(0xffffffffu, c, jj + 3);
            float w0 = __shfl_sync(0xffffffffu, w, jj);
            float w1 = __shfl_sync(0xffffffffu, w, jj + 1);
            float w2 = __shfl_sync(0xffffffffu, w, jj + 2);
            float w3 = __shfl_sync(0xffffffffu, w, jj + 3);
            if (lane < 10) {
                float4 v0 = Q[(size_t)c0 * 20 + 10 + lane];
                float4 v1 = Q[(size_t)c1 * 20 + 10 + lane];
                float4 v2 = Q[(size_t)c2 * 20 + 10 + lane];
                float4 v3 = Q[(size_t)c3 * 20 + 10 + lane];
                acc.x += w0 * v0.x; acc.y += w0 * v0.y; acc.z += w0 * v0.z; acc.w += w0 * v0.w;
                acc.x += w1 * v1.x; acc.y += w1 * v1.y; acc.z += w1 * v1.z; acc.w += w1 * v1.w;
                acc.x += w2 * v2.x; acc.y += w2 * v2.y; acc.z += w2 * v2.z; acc.w += w2 * v2.w;
                acc.x += w3 * v3.x; acc.y += w3 * v3.y; acc.z += w3 * v3.z; acc.w += w3 * v3.w;
            }
        }
        for (; jj < m; jj++) {
            int   cc = __shfl_sync(0xffffffffu, c, jj);
            float ww = __shfl_sync(0xffffffffu, w, jj);
            if (lane < 10) {
                float4 v = Q[(size_t)cc * 20 + 10 + lane];
                acc.x += ww * v.x; acc.y += ww * v.y; acc.z += ww * v.z; acc.w += ww * v.w;
            }
        }
    }

    // ---- fused epilogue: v = P0 + Q1 + r + b2 ; log_softmax ----
    float4 v = make_float4(0.f, 0.f, 0.f, 0.f);
    if (lane < 10) {
        float4 a  = ((const float4*)g_p0)[(size_t)node * 10 + lane];
        float4 q1 = Q[(size_t)node * 20 + lane];
        float4 bb = ((const float4*)b2)[lane];
        v.x = a.x + q1.x + acc.x + bb.x;
        v.y = a.y + q1.y + acc.y + bb.y;
        v.z = a.z + q1.z + acc.z + bb.z;
        v.w = a.w + q1.w + acc.w + bb.w;
    }

    float m = (lane < 10) ? fmaxf(fmaxf(v.x, v.y), fmaxf(v.z, v.w)) : -1e30f;
#pragma unroll
    for (int o = 16; o > 0; o >>= 1) m = fmaxf(m, __shfl_xor_sync(0xffffffffu, m, o));
    float s = (lane < 10) ? (expf(v.x - m) + expf(v.y - m) + expf(v.z - m) + expf(v.w - m)) : 0.f;
#pragma unroll
    for (int o = 16; o > 0; o >>= 1) s += __shfl_xor_sync(0xffffffffu, s, o);
    float z = m + logf(s);

    if (lane < 10) {
        float4 o4 = make_float4(v.x - z, v.y - z, v.z - z, v.w - z);
        *(float4*)(out + (size_t)node * NC + lane * 4) = o4;
    }
}

// ---------------- launch ----------------
extern "C" void kernel_launch(void* const* d_in, const int* in_sizes, int n_in,
                              void* d_out, int out_size) {
    const float* x    = (const float*)d_in[0];
    const int*   erow = (const int*)  d_in[1];
    const int*   ecol = (const int*)  d_in[2];
    const float* W1   = (const float*)d_in[3];
    const float* b1   = (const float*)d_in[4];
    const float* W2   = (const float*)d_in[5];
    const float* b2   = (const float*)d_in[6];
    float* out = (float*)d_out;

    int n = in_sizes[0] / FD;   // 50000
    int e = in_sizes[1];        // 1600000
    (void)n_in; (void)out_size;

    int nb  = (n + 1023) / 1024;
    int nwb = (n + 7) / 8;

    // order chosen so launch #6 (the one ncu samples) is k_gemm1
    k_w1t    <<<dim3(16, 16), dim3(32, 8)>>>(W1);                 // 1
    k_buildwr<<<(NCOL * FD + 255) / 256, 256>>>(W2);              // 2
    k_init   <<<(n + 255) / 256, 256>>>(n);                       // 3
    k_count  <<<(e + 255) / 256, 256>>>(erow, ecol, e);           // 4
    k_scan1  <<<nb, 256>>>(n);                                    // 5
    dim3 g1(FD / 128, (n + 127) / 128);
    k_gemm1  <<<g1, 256>>>(x, b1, n);                             // 6  <- profiled
    k_scan3  <<<nb, 256>>>(nb, n);                                // 7
    k_scatter<<<(e + 255) / 256, 256>>>(erow, ecol, e);           // 8
    k_gemm2a <<<(n + 127) / 128, 256>>>(n);                       // 9
    k_spmmA  <<<nwb, 256>>>(n);                                   // 10
    k_spmmB_final<<<nwb, 256>>>(b2, out, n);                      // 11
}

// round 14
// speedup vs baseline: 4.2456x; 1.0397x over previous
#include <cuda_runtime.h>
#include <cuda_bf16.h>
#include <math.h>
#include <stdint.h>

#define NN 50000
#define EE 1600000
#define FD 512
#define NC 40
#define NCOL 120   // [Wa|Wb|Wc] columns

// ---------------- device scratch ----------------
__device__ float g_deg[NN];
__device__ float g_dinv[NN];
__device__ __align__(16) int g_cnt[NN];
__device__ int   g_fill[NN];
__device__ int   g_rowptr[NN + 1];
__device__ int   g_csrcol[EE];
__device__ int   g_bsum[64];
__device__ __align__(16) __nv_bfloat16 g_tb[(size_t)NN * FD];  // relu(xW1+b1), bf16
__device__ __align__(16) float g_p0 [(size_t)NN * 40];   // t*Wa
__device__ __align__(16) float g_p12[(size_t)NN * 80];   // [t*Wb | t*Wc] fp32
__device__ __align__(16) __nv_bfloat16 g_p12b[(size_t)NN * 80]; // bf16 shadow for gather
__device__ __align__(16) float g_q12[(size_t)NN * 80];   // [A p1 | A p2] fp32
__device__ __align__(16) __nv_bfloat16 g_q2b[(size_t)NN * 40];  // bf16 shadow of A p2
__device__ __align__(16) __nv_bfloat16 g_wrb[NCOL * FD]; // [Wa|Wb|Wc]^T bf16 [n][k]
__device__ __align__(16) __nv_bfloat16 g_w1t[FD * FD];   // W1 transposed, bf16 [n][k]

__device__ __forceinline__ float bf_lo(uint32_t u) { return __uint_as_float(u << 16); }
__device__ __forceinline__ float bf_hi(uint32_t u) { return __uint_as_float(u & 0xffff0000u); }

// ---------------- preprocessing ----------------
__global__ void k_init(int n) {
    int i = blockIdx.x * blockDim.x + threadIdx.x;
    if (i < n) { g_deg[i] = 1.0f; g_cnt[i] = 0; g_fill[i] = 0; }
}

// 4 edges per thread, int4 loads
__global__ void k_count(const int* __restrict__ row, const int* __restrict__ col, int e) {
    int i = (blockIdx.x * blockDim.x + threadIdx.x) * 4;
    if (i + 3 < e) {
        int4 r = *(const int4*)(row + i);
        int4 c = *(const int4*)(col + i);
        atomicAdd(&g_deg[c.x], 1.0f); atomicAdd(&g_cnt[r.x], 1);
        atomicAdd(&g_deg[c.y], 1.0f); atomicAdd(&g_cnt[r.y], 1);
        atomicAdd(&g_deg[c.z], 1.0f); atomicAdd(&g_cnt[r.z], 1);
        atomicAdd(&g_deg[c.w], 1.0f); atomicAdd(&g_cnt[r.w], 1);
    } else {
        for (int j = 0; j < 4; j++)
            if (i + j < e) {
                atomicAdd(&g_deg[col[i + j]], 1.0f);
                atomicAdd(&g_cnt[row[i + j]], 1);
            }
    }
}

// scan phase 1 + dinv fused
__global__ void k_scan1(int n) {
    __shared__ int sh[256];
    int b = blockIdx.x, t = threadIdx.x;
    int i = b * 1024 + t * 4;
    for (int j = 0; j < 4; j++)
        if (i + j < n) g_dinv[i + j] = rsqrtf(g_deg[i + j]);
    int s = 0;
    if (i + 3 < n) { int4 v = *(const int4*)(g_cnt + i); s = v.x + v.y + v.z + v.w; }
    else { for (int j = 0; j < 4; j++) if (i + j < n) s += g_cnt[i + j]; }
    sh[t] = s; __syncthreads();
    for (int o = 128; o > 0; o >>= 1) { if (t < o) sh[t] += sh[t + o]; __syncthreads(); }
    if (t == 0) g_bsum[b] = sh[0];
}

// scan phase 2+3 fused
__global__ void k_scan3(int nb, int n) {
    __shared__ int sh[256];
    int b = blockIdx.x, t = threadIdx.x;
    int i = b * 1024 + t * 4;
    int c0 = 0, c1 = 0, c2 = 0, c3 = 0;
    if (i + 3 < n) { int4 v = *(const int4*)(g_cnt + i); c0 = v.x; c1 = v.y; c2 = v.z; c3 = v.w; }
    else {
        if (i     < n) c0 = g_cnt[i];
        if (i + 1 < n) c1 = g_cnt[i + 1];
        if (i + 2 < n) c2 = g_cnt[i + 2];
        if (i + 3 < n) c3 = g_cnt[i + 3];
    }
    int s = c0 + c1 + c2 + c3;
    sh[t] = s; __syncthreads();
    for (int o = 1; o < 256; o <<= 1) {
        int v = (t >= o) ? sh[t - o] : 0;
        __syncthreads();
        sh[t] += v;
        __syncthreads();
    }
    int bpre = 0;
    for (int bb = 0; bb < b; bb++) bpre += g_bsum[bb];
    if (b == 0 && t == 0) {
        int tot = 0;
        for (int bb = 0; bb < nb; bb++) tot += g_bsum[bb];
        g_rowptr[n] = tot;
    }
    int base = bpre + ((t > 0) ? sh[t - 1] : 0);
    if (i     < n) { g_rowptr[i]     = base; base += c0; }
    if (i + 1 < n) { g_rowptr[i + 1] = base; base += c1; }
    if (i + 2 < n) { g_rowptr[i + 2] = base; base += c2; }
    if (i + 3 < n) { g_rowptr[i + 3] = base; }
}

__global__ void k_scatter(const int* __restrict__ row, const int* __restrict__ col, int e) {
    int i = blockIdx.x * blockDim.x + threadIdx.x;
    if (i < e) {
        int r = row[i];
        int pos = g_rowptr[r] + atomicAdd(&g_fill[r], 1);
        g_csrcol[pos] = col[i];
    }
}

// ---------------- W1 transpose -> bf16 [n][k] ----------------
__global__ void k_w1t(const float* __restrict__ W1) {
    __shared__ float tile[32][33];
    int bx = blockIdx.x * 32, by = blockIdx.y * 32;
    int tx = threadIdx.x, ty = threadIdx.y;
#pragma unroll
    for (int i = 0; i < 4; i++)
        tile[ty + i * 8][tx] = W1[(size_t)(by + ty + i * 8) * FD + bx + tx];
    __syncthreads();
#pragma unroll
    for (int i = 0; i < 4; i++)
        g_w1t[(size_t)(bx + ty + i * 8) * FD + by + tx] =
            __float2bfloat16(tile[tx][ty + i * 8]);
}

// ---------------- bf16 HMMA helpers ----------------
__device__ __forceinline__ void mma_bf16(float* d, const uint32_t* a, const uint32_t* b) {
    asm volatile(
        "mma.sync.aligned.m16n8k16.row.col.f32.bf16.bf16.f32 "
        "{%0,%1,%2,%3}, {%4,%5,%6,%7}, {%8,%9}, {%0,%1,%2,%3};\n"
        : "+f"(d[0]), "+f"(d[1]), "+f"(d[2]), "+f"(d[3])
        : "r"(a[0]), "r"(a[1]), "r"(a[2]), "r"(a[3]), "r"(b[0]), "r"(b[1]));
}

#define BM 128
#define BN 128
#define BK 32
#define ASTR 40

// ---------------- GEMM1: tb = bf16(relu(x @ W1 + b1)) ----------------
__global__ __launch_bounds__(256, 2) void k_gemm1(const float* __restrict__ A,
                                                  const float* __restrict__ bias, int n) {
    __shared__ __nv_bfloat16 As[BM * ASTR];
    __shared__ __nv_bfloat16 Bs[BN * ASTR];
    int tid = threadIdx.x;
    int lane = tid & 31, warp = tid >> 5;
    int wm = (warp & 3) * 32;
    int wn = (warp >> 2) * 64;
    int r0 = blockIdx.y * BM, c0 = blockIdx.x * BN;

    float acc[2][8][4];
#pragma unroll
    for (int mi = 0; mi < 2; mi++)
#pragma unroll
        for (int ni = 0; ni < 8; ni++)
#pragma unroll
            for (int j = 0; j < 4; j++) acc[mi][ni][j] = 0.f;

    for (int k0 = 0; k0 < FD; k0 += BK) {
#pragma unroll
        for (int it = 0; it < 4; it++) {
            int idx = tid + it * 256;
            int row = idx >> 3;
            int q   = idx & 7;
            int gr  = r0 + row;
            float4 v = (gr < n) ? *(const float4*)(A + (size_t)gr * FD + k0 + q * 4)
                                : make_float4(0.f, 0.f, 0.f, 0.f);
            __nv_bfloat162 p0 = __floats2bfloat162_rn(v.x, v.y);
            __nv_bfloat162 p1 = __floats2bfloat162_rn(v.z, v.w);
            *(uint2*)(As + row * ASTR + q * 4) = make_uint2(*(uint32_t*)&p0, *(uint32_t*)&p1);
        }
#pragma unroll
        for (int it = 0; it < 2; it++) {
            int idx = tid + it * 256;
            int row = idx >> 2;
            int q   = idx & 3;
            uint4 v = *(const uint4*)(g_w1t + (size_t)(c0 + row) * FD + k0 + q * 8);
            *(uint4*)(Bs + row * ASTR + q * 8) = v;
        }
        __syncthreads();

        int g = lane >> 2, q = lane & 3;
#pragma unroll
        for (int ks = 0; ks < 2; ks++) {
            uint32_t afr[2][4], bfr[8][2];
#pragma unroll
            for (int mi = 0; mi < 2; mi++) {
                const __nv_bfloat16* base = As + (wm + mi * 16 + g) * ASTR + ks * 16 + q * 2;
                afr[mi][0] = *(const uint32_t*)(base);
                afr[mi][1] = *(const uint32_t*)(base + 8 * ASTR);
                afr[mi][2] = *(const uint32_t*)(base + 8);
                afr[mi][3] = *(const uint32_t*)(base + 8 * ASTR + 8);
            }
#pragma unroll
            for (int ni = 0; ni < 8; ni++) {
                const __nv_bfloat16* base = Bs + (wn + ni * 8 + g) * ASTR + ks * 16 + q * 2;
                bfr[ni][0] = *(const uint32_t*)(base);
                bfr[ni][1] = *(const uint32_t*)(base + 8);
            }
#pragma unroll
            for (int mi = 0; mi < 2; mi++)
#pragma unroll
                for (int ni = 0; ni < 8; ni++)
                    mma_bf16(acc[mi][ni], afr[mi], bfr[ni]);
        }
        __syncthreads();
    }

    int g = lane >> 2, q = lane & 3;
#pragma unroll
    for (int mi = 0; mi < 2; mi++) {
        int row = r0 + wm + mi * 16 + g;
#pragma unroll
        for (int ni = 0; ni < 8; ni++) {
            int col = c0 + wn + ni * 8 + q * 2;
            float bb0 = bias[col], bb1 = bias[col + 1];
            if (row < n) {
                *(__nv_bfloat162*)(g_tb + (size_t)row * FD + col) =
                    __floats2bfloat162_rn(fmaxf(acc[mi][ni][0] + bb0, 0.f),
                                          fmaxf(acc[mi][ni][1] + bb1, 0.f));
            }
            if (row + 8 < n) {
                *(__nv_bfloat162*)(g_tb + (size_t)(row + 8) * FD + col) =
                    __floats2bfloat162_rn(fmaxf(acc[mi][ni][2] + bb0, 0.f),
                                          fmaxf(acc[mi][ni][3] + bb1, 0.f));
            }
        }
    }
}

// ---------------- build Wr^T bf16 [120][512] ----------------
__global__ void k_buildwr(const float* __restrict__ W2) {
    int idx = blockIdx.x * blockDim.x + threadIdx.x;
    if (idx >= NCOL * FD) return;
    int c = idx / FD, k = idx % FD;
    float v;
    if (c < 40)       v = W2[k * NC + c]               + W2[(k + 512) * NC + c];
    else if (c < 80)  v = W2[(k + 1024) * NC + c - 40] + W2[(k + 1536) * NC + c - 40];
    else              v = W2[(k + 2048) * NC + c - 80];
    g_wrb[idx] = __float2bfloat16(v);
}

// ---------------- bf16 GEMM2a: P = t @ Wr  [n,512]x[512,120] ----------------
__global__ __launch_bounds__(256) void k_gemm2a(int n) {
    __shared__ __nv_bfloat16 As[BM * ASTR];
    __shared__ __nv_bfloat16 Ws[NCOL * ASTR];

    int tid  = threadIdx.x;
    int lane = tid & 31, warp = tid >> 5;
    int r0   = blockIdx.x * 128;

    float acc[15][4];
#pragma unroll
    for (int t = 0; t < 15; t++)
#pragma unroll
        for (int j = 0; j < 4; j++) acc[t][j] = 0.f;

    for (int k0 = 0; k0 < FD; k0 += BK) {
#pragma unroll
        for (int it = 0; it < 2; it++) {
            int idx = tid + it * 256;
            int row = idx >> 2;
            int q   = idx & 3;
            int gr  = r0 + row;
            uint4 v = (gr < n) ? *(const uint4*)(g_tb + (size_t)gr * FD + k0 + q * 8)
                               : make_uint4(0, 0, 0, 0);
            *(uint4*)(As + row * ASTR + q * 8) = v;
        }
        {
            int idx = tid;
            if (idx < 480) {
                int row = idx >> 2, q = idx & 3;
                uint4 v = *(const uint4*)(g_wrb + (size_t)row * FD + k0 + q * 8);
                *(uint4*)(Ws + row * ASTR + q * 8) = v;
            }
            idx = tid + 256;
            if (idx < 480) {
                int row = idx >> 2, q = idx & 3;
                uint4 v = *(const uint4*)(g_wrb + (size_t)row * FD + k0 + q * 8);
                *(uint4*)(Ws + row * ASTR + q * 8) = v;
            }
        }
        __syncthreads();

        int g = lane >> 2, q = lane & 3;
#pragma unroll
        for (int ks = 0; ks < 2; ks++) {
            uint32_t a[4];
            const __nv_bfloat16* abase = As + (warp * 16 + g) * ASTR + ks * 16 + q * 2;
            a[0] = *(const uint32_t*)(abase);
            a[1] = *(const uint32_t*)(abase + 8 * ASTR);
            a[2] = *(const uint32_t*)(abase + 8);
            a[3] = *(const uint32_t*)(abase + 8 * ASTR + 8);
#pragma unroll
            for (int t = 0; t < 15; t++) {
                uint32_t b[2];
                const __nv_bfloat16* bbase = Ws + (t * 8 + g) * ASTR + ks * 16 + q * 2;
                b[0] = *(const uint32_t*)(bbase);
                b[1] = *(const uint32_t*)(bbase + 8);
                mma_bf16(acc[t], a, b);
            }
        }
        __syncthreads();
    }

    // epilogue: P0 fp32 (c<40); P12 fp32 + bf16 shadow (c>=40)
    int g = lane >> 2, q = lane & 3;
    int rlo = r0 + warp * 16 + g;
    int rhi = rlo + 8;
#pragma unroll
    for (int t = 0; t < 15; t++) {
        int c = t * 8 + q * 2;
        if (rlo < n) {
            float2 v = make_float2(acc[t][0], acc[t][1]);
            if (c < 40) *(float2*)(g_p0 + (size_t)rlo * 40 + c) = v;
            else {
                *(float2*)(g_p12 + (size_t)rlo * 80 + c - 40) = v;
                __nv_bfloat162 p = __floats2bfloat162_rn(v.x, v.y);
                *(uint32_t*)(g_p12b + (size_t)rlo * 80 + c - 40) = *(uint32_t*)&p;
            }
        }
        if (rhi < n) {
            float2 v = make_float2(acc[t][2], acc[t][3]);
            if (c < 40) *(float2*)(g_p0 + (size_t)rhi * 40 + c) = v;
            else {
                *(float2*)(g_p12 + (size_t)rhi * 80 + c - 40) = v;
                __nv_bfloat162 p = __floats2bfloat162_rn(v.x, v.y);
                *(uint32_t*)(g_p12b + (size_t)rhi * 80 + c - 40) = *(uint32_t*)&p;
            }
        }
    }
}

// ---------------- SpMM-A: Q12 = Ahat @ P12 (bf16 gather), warp per node ----------------
__global__ __launch_bounds__(256) void k_spmmA(int n) {
    int node = blockIdx.x * 8 + (threadIdx.x >> 5);
    int lane = threadIdx.x & 31;
    if (node >= n) return;

    float di = g_dinv[node];
    float4 acc = make_float4(0, 0, 0, 0);
    if (lane < 20) {
        float4 s = ((const float4*)g_p12)[(size_t)node * 20 + lane];   // fp32 self term
        float w = di * di;
        acc.x = s.x * w; acc.y = s.y * w; acc.z = s.z * w; acc.w = s.w * w;
    }

    const uint2* Pb = (const uint2*)g_p12b;   // row = 20 uint2
    int beg = g_rowptr[node], end = g_rowptr[node + 1];
    for (int b = beg; b < end; b += 32) {
        int m = end - b; if (m > 32) m = 32;
        int c = 0; float w = 0.f;
        if (lane < m) { c = g_csrcol[b + lane]; w = di * g_dinv[c]; }
        int jj = 0;
        for (; jj + 4 <= m; jj += 4) {
            int   c0 = __shfl_sync(0xffffffffu, c, jj);
            int   c1 = __shfl_sync(0xffffffffu, c, jj + 1);
            int   c2 = __shfl_sync(0xffffffffu, c, jj + 2);
            int   c3 = __shfl_sync(0xffffffffu, c, jj + 3);
            float w0 = __shfl_sync(0xffffffffu, w, jj);
            float w1 = __shfl_sync(0xffffffffu, w, jj + 1);
            float w2 = __shfl_sync(0xffffffffu, w, jj + 2);
            float w3 = __shfl_sync(0xffffffffu, w, jj + 3);
            if (lane < 20) {
                uint2 v0 = Pb[(size_t)c0 * 20 + lane];
                uint2 v1 = Pb[(size_t)c1 * 20 + lane];
                uint2 v2 = Pb[(size_t)c2 * 20 + lane];
                uint2 v3 = Pb[(size_t)c3 * 20 + lane];
                acc.x += w0 * bf_lo(v0.x); acc.y += w0 * bf_hi(v0.x);
                acc.z += w0 * bf_lo(v0.y); acc.w += w0 * bf_hi(v0.y);
                acc.x += w1 * bf_lo(v1.x); acc.y += w1 * bf_hi(v1.x);
                acc.z += w1 * bf_lo(v1.y); acc.w += w1 * bf_hi(v1.y);
                acc.x += w2 * bf_lo(v2.x); acc.y += w2 * bf_hi(v2.x);
                acc.z += w2 * bf_lo(v2.y); acc.w += w2 * bf_hi(v2.y);
                acc.x += w3 * bf_lo(v3.x); acc.y += w3 * bf_hi(v3.x);
                acc.z += w3 * bf_lo(v3.y); acc.w += w3 * bf_hi(v3.y);
            }
        }
        for (; jj < m; jj++) {
            int   cc = __shfl_sync(0xffffffffu, c, jj);
            float ww = __shfl_sync(0xffffffffu, w, jj);
            if (lane < 20) {
                uint2 v = Pb[(size_t)cc * 20 + lane];
                acc.x += ww * bf_lo(v.x); acc.y += ww * bf_hi(v.x);
                acc.z += ww * bf_lo(v.y); acc.w += ww * bf_hi(v.y);
            }
        }
    }
    if (lane < 20) {
        ((float4*)g_q12)[(size_t)node * 20 + lane] = acc;
        if (lane >= 10) {   // lanes 10..19 hold Q2 -> bf16 shadow
            __nv_bfloat162 p0 = __floats2bfloat162_rn(acc.x, acc.y);
            __nv_bfloat162 p1 = __floats2bfloat162_rn(acc.z, acc.w);
            ((uint2*)g_q2b)[(size_t)node * 10 + (lane - 10)] =
                make_uint2(*(uint32_t*)&p0, *(uint32_t*)&p1);
        }
    }
}

// ---------------- SpMM-B (bf16 gather) fused with final log_softmax ----------------
__global__ __launch_bounds__(256) void k_spmmB_final(const float* __restrict__ b2,
                                                     float* __restrict__ out, int n) {
    int node = blockIdx.x * 8 + (threadIdx.x >> 5);
    int lane = threadIdx.x & 31;
    if (node >= n) return;

    float di = g_dinv[node];
    const float4* Q = (const float4*)g_q12;
    float4 acc = make_float4(0, 0, 0, 0);
    if (lane < 10) {
        float4 s = Q[(size_t)node * 20 + 10 + lane];   // fp32 self term
        float w = di * di;
        acc.x = s.x * w; acc.y = s.y * w; acc.z = s.z * w; acc.w = s.w * w;
    }

    const uint2* Qb = (const uint2*)g_q2b;   // row = 10 uint2
    int beg = g_rowptr[node], end = g_rowptr[node + 1];
    for (int b = beg; b < end; b += 32) {
        int m = end - b; if (m > 32) m = 32;
        int c = 0; float w = 0.f;
        if (lane < m) { c = g_csrcol[b + lane]; w = di * g_dinv[c]; }
        int jj = 0;
        for (; jj + 4 <= m; jj += 4) {
            int   c0 = __shfl_sync(0xffffffffu, c, jj);
            int   c1 = __shfl_sync(0xffffffffu, c, jj + 1);
            int   c2 = __shfl_sync(0xffffffffu, c, jj + 2);
            int   c3 = __shfl_sync(0xffffffffu, c, jj + 3);
            float w0 = __shfl_sync(0xffffffffu, w, jj);
            float w1 = __shfl_sync(0xffffffffu, w, jj + 1);
            float w2 = __shfl_sync(0xffffffffu, w, jj + 2);
            float w3 = __shfl_sync(0xffffffffu, w, jj + 3);
            if (lane < 10) {
                uint2 v0 = Qb[(size_t)c0 * 10 + lane];
                uint2 v1 = Qb[(size_t)c1 * 10 + lane];
                uint2 v2 = Qb[(size_t)c2 * 10 + lane];
                uint2 v3 = Qb[(size_t)c3 * 10 + lane];
                acc.x += w0 * bf_lo(v0.x); acc.y += w0 * bf_hi(v0.x);
                acc.z += w0 * bf_lo(v0.y); acc.w += w0 * bf_hi(v0.y);
                acc.x += w1 * bf_lo(v1.x); acc.y += w1 * bf_hi(v1.x);
                acc.z += w1 * bf_lo(v1.y); acc.w += w1 * bf_hi(v1.y);
                acc.x += w2 * bf_lo(v2.x); acc.y += w2 * bf_hi(v2.x);
                acc.z += w2 * bf_lo(v2.y); acc.w += w2 * bf_hi(v2.y);
                acc.x += w3 * bf_lo(v3.x); acc.y += w3 * bf_hi(v3.x);
                acc.z += w3 * bf_lo(v3.y); acc.w += w3 * bf_hi(v3.y);
            }
        }
        for (; jj < m; jj++) {
            int   cc = __shfl_sync(0xffffffffu, c, jj);
            float ww = __shfl_sync(0xffffffffu, w, jj);
            if (lane < 10) {
                uint2 v = Qb[(size_t)cc * 10 + lane];
                acc.x += ww * bf_lo(v.x); acc.y += ww * bf_hi(v.x);
                acc.z += ww * bf_lo(v.y); acc.w += ww * bf_hi(v.y);
            }
        }
    }

    // ---- fused epilogue: v = P0 + Q1 + r + b2 ; log_softmax ----
    float4 v = make_float4(0.f, 0.f, 0.f, 0.f);
    if (lane < 10) {
        float4 a  = ((const float4*)g_p0)[(size_t)node * 10 + lane];
        float4 q1 = Q[(size_t)node * 20 + lane];
        float4 bb = ((const float4*)b2)[lane];
        v.x = a.x + q1.x + acc.x + bb.x;
        v.y = a.y + q1.y + acc.y + bb.y;
        v.z = a.z + q1.z + acc.z + bb.z;
        v.w = a.w + q1.w + acc.w + bb.w;
    }

    float m = (lane < 10) ? fmaxf(fmaxf(v.x, v.y), fmaxf(v.z, v.w)) : -1e30f;
#pragma unroll
    for (int o = 16; o > 0; o >>= 1) m = fmaxf(m, __shfl_xor_sync(0xffffffffu, m, o));
    float s = (lane < 10) ? (expf(v.x - m) + expf(v.y - m) + expf(v.z - m) + expf(v.w - m)) : 0.f;
#pragma unroll
    for (int o = 16; o > 0; o >>= 1) s += __shfl_xor_sync(0xffffffffu, s, o);
    float z = m + logf(s);

    if (lane < 10) {
        float4 o4 = make_float4(v.x - z, v.y - z, v.z - z, v.w - z);
        *(float4*)(out + (size_t)node * NC + lane * 4) = o4;
    }
}

// ---------------- launch ----------------
extern "C" void kernel_launch(void* const* d_in, const int* in_sizes, int n_in,
                              void* d_out, int out_size) {
    const float* x    = (const float*)d_in[0];
    const int*   erow = (const int*)  d_in[1];
    const int*   ecol = (const int*)  d_in[2];
    const float* W1   = (const float*)d_in[3];
    const float* b1   = (const float*)d_in[4];
    const float* W2   = (const float*)d_in[5];
    const float* b2   = (const float*)d_in[6];
    float* out = (float*)d_out;

    int n = in_sizes[0] / FD;   // 50000
    int e = in_sizes[1];        // 1600000
    (void)n_in; (void)out_size;

    int nb  = (n + 1023) / 1024;
    int nwb = (n + 7) / 8;

    k_w1t    <<<dim3(16, 16), dim3(32, 8)>>>(W1);                 // 1
    k_buildwr<<<(NCOL * FD + 255) / 256, 256>>>(W2);              // 2
    k_init   <<<(n + 255) / 256, 256>>>(n);                       // 3
    k_count  <<<(e / 4 + 255) / 256, 256>>>(erow, ecol, e);       // 4
    k_scan1  <<<nb, 256>>>(n);                                    // 5
    dim3 g1(FD / 128, (n + 127) / 128);
    k_gemm1  <<<g1, 256>>>(x, b1, n);                             // 6
    k_scan3  <<<nb, 256>>>(nb, n);                                // 7
    k_scatter<<<(e + 255) / 256, 256>>>(erow, ecol, e);           // 8
    k_gemm2a <<<(n + 127) / 128, 256>>>(n);                       // 9
    k_spmmA  <<<nwb, 256>>>(n);                                   // 10
    k_spmmB_final<<<nwb, 256>>>(b2, out, n);                      // 11
}